// round 1
// baseline (speedup 1.0000x reference)
#include <cuda_runtime.h>
#include <math.h>

#define NDIM 4096
#define DDIM 1024
#define BM 128
#define BN 128
#define BK 16

// ---------------- scratch (device globals: allocation-guard safe) ----------------
__device__ float g_S[(size_t)NDIM * NDIM];            // 64 MB attention scores/probs
__device__ float g_H4[(size_t)NDIM * 3 * DDIM];       // 48 MB concat buffer
__device__ unsigned char g_MT[(size_t)NDIM * NDIM];   // 16 MB transposed byte mask for B_low

// ---------------- packed f32x2 FMA (FFMA2) ----------------
union F2 { float2 f; unsigned long long u; };

__device__ __forceinline__ void ffma2(F2& d, const F2& a, const F2& b) {
    asm("fma.rn.f32x2 %0, %1, %2, %0;" : "+l"(d.u) : "l"(a.u), "l"(b.u));
}

// ============================================================================
// GEMM NT:  C[M,N] = alpha * A[M,K] @ B[N,K]^T   (+bias, +tanh optional)
// A row-major (lda = K stride), B row-major (ldb = K stride), C row-major.
// Grid: (N/128, M/128), 256 threads. Each thread: 8x8 outputs via FFMA2.
// ============================================================================
__global__ void __launch_bounds__(256, 2) gemm_nt_kernel(
    const float* __restrict__ A, int lda,
    const float* __restrict__ B, int ldb,
    float* __restrict__ C, int ldc,
    int K, float alpha,
    const float* __restrict__ bias, int do_tanh)
{
    __shared__ __align__(16) float As[BK][BM + 4];
    __shared__ __align__(16) float Bs[BK][BN + 4];

    const int t  = threadIdx.x;
    const int m0 = blockIdx.y * BM;
    const int n0 = blockIdx.x * BN;
    const int tm = t >> 4;            // 0..15
    const int tn = t & 15;            // 0..15
    const int lrow = t >> 2;          // 0..63
    const int lk   = (t & 3) * 4;     // 0,4,8,12

    F2 acc[8][4];
#pragma unroll
    for (int i = 0; i < 8; i++)
#pragma unroll
        for (int j = 0; j < 4; j++) { acc[i][j].f.x = 0.f; acc[i][j].f.y = 0.f; }

    const float* Ap0 = A + (size_t)(m0 + lrow) * lda + lk;
    const float* Ap1 = A + (size_t)(m0 + lrow + 64) * lda + lk;
    const float* Bp0 = B + (size_t)(n0 + lrow) * ldb + lk;
    const float* Bp1 = B + (size_t)(n0 + lrow + 64) * ldb + lk;

    for (int k0 = 0; k0 < K; k0 += BK) {
        float4 va0 = *(const float4*)(Ap0 + k0);
        float4 va1 = *(const float4*)(Ap1 + k0);
        float4 vb0 = *(const float4*)(Bp0 + k0);
        float4 vb1 = *(const float4*)(Bp1 + k0);
        __syncthreads();   // previous tile fully consumed
        As[lk+0][lrow]    = va0.x; As[lk+1][lrow]    = va0.y;
        As[lk+2][lrow]    = va0.z; As[lk+3][lrow]    = va0.w;
        As[lk+0][lrow+64] = va1.x; As[lk+1][lrow+64] = va1.y;
        As[lk+2][lrow+64] = va1.z; As[lk+3][lrow+64] = va1.w;
        Bs[lk+0][lrow]    = vb0.x; Bs[lk+1][lrow]    = vb0.y;
        Bs[lk+2][lrow]    = vb0.z; Bs[lk+3][lrow]    = vb0.w;
        Bs[lk+0][lrow+64] = vb1.x; Bs[lk+1][lrow+64] = vb1.y;
        Bs[lk+2][lrow+64] = vb1.z; Bs[lk+3][lrow+64] = vb1.w;
        __syncthreads();

#pragma unroll
        for (int k = 0; k < BK; k++) {
            float a[8];
            *(float4*)&a[0] = *(const float4*)&As[k][tm * 8];
            *(float4*)&a[4] = *(const float4*)&As[k][tm * 8 + 4];
            F2 bb[4];
            bb[0].f = *(const float2*)&Bs[k][tn * 8 + 0];
            bb[1].f = *(const float2*)&Bs[k][tn * 8 + 2];
            bb[2].f = *(const float2*)&Bs[k][tn * 8 + 4];
            bb[3].f = *(const float2*)&Bs[k][tn * 8 + 6];
#pragma unroll
            for (int i = 0; i < 8; i++) {
                F2 aa; aa.f.x = a[i]; aa.f.y = a[i];
#pragma unroll
                for (int j = 0; j < 4; j++) ffma2(acc[i][j], aa, bb[j]);
            }
        }
    }

#pragma unroll
    for (int i = 0; i < 8; i++) {
        const int row = m0 + tm * 8 + i;
        float* Crow = C + (size_t)row * ldc + n0 + tn * 8;
#pragma unroll
        for (int j = 0; j < 4; j++) {
            float2 v = acc[i][j].f;
            v.x *= alpha; v.y *= alpha;
            if (bias) {
                v.x += bias[n0 + tn * 8 + j * 2];
                v.y += bias[n0 + tn * 8 + j * 2 + 1];
            }
            if (do_tanh) { v.x = tanhf(v.x); v.y = tanhf(v.y); }
            *(float2*)(Crow + j * 2) = v;
        }
    }
}

// ============================================================================
// GEMM NN:  C[M,N] = A[M,K] @ B[K,N]
// A row-major (lda = K stride), B row-major (ldb = N stride).
// Grid: (N/128, M/128), 256 threads.
// ============================================================================
__global__ void __launch_bounds__(256, 2) gemm_nn_kernel(
    const float* __restrict__ A, int lda,
    const float* __restrict__ B, int ldb,
    float* __restrict__ C, int ldc,
    int K)
{
    __shared__ __align__(16) float As[BK][BM + 4];
    __shared__ __align__(16) float Bs[BK][BN + 4];

    const int t  = threadIdx.x;
    const int m0 = blockIdx.y * BM;
    const int n0 = blockIdx.x * BN;
    const int tm = t >> 4;
    const int tn = t & 15;
    const int lrow = t >> 2;          // 0..63  (A loads)
    const int lk   = (t & 3) * 4;
    const int bkr  = t >> 5;          // 0..7   (B loads)
    const int bnc  = (t & 31) * 4;    // 0..124

    F2 acc[8][4];
#pragma unroll
    for (int i = 0; i < 8; i++)
#pragma unroll
        for (int j = 0; j < 4; j++) { acc[i][j].f.x = 0.f; acc[i][j].f.y = 0.f; }

    const float* Ap0 = A + (size_t)(m0 + lrow) * lda + lk;
    const float* Ap1 = A + (size_t)(m0 + lrow + 64) * lda + lk;

    for (int k0 = 0; k0 < K; k0 += BK) {
        float4 va0 = *(const float4*)(Ap0 + k0);
        float4 va1 = *(const float4*)(Ap1 + k0);
        float4 vb0 = *(const float4*)&B[(size_t)(k0 + bkr)     * ldb + n0 + bnc];
        float4 vb1 = *(const float4*)&B[(size_t)(k0 + bkr + 8) * ldb + n0 + bnc];
        __syncthreads();
        As[lk+0][lrow]    = va0.x; As[lk+1][lrow]    = va0.y;
        As[lk+2][lrow]    = va0.z; As[lk+3][lrow]    = va0.w;
        As[lk+0][lrow+64] = va1.x; As[lk+1][lrow+64] = va1.y;
        As[lk+2][lrow+64] = va1.z; As[lk+3][lrow+64] = va1.w;
        *(float4*)&Bs[bkr][bnc]     = vb0;
        *(float4*)&Bs[bkr + 8][bnc] = vb1;
        __syncthreads();

#pragma unroll
        for (int k = 0; k < BK; k++) {
            float a[8];
            *(float4*)&a[0] = *(const float4*)&As[k][tm * 8];
            *(float4*)&a[4] = *(const float4*)&As[k][tm * 8 + 4];
            F2 bb[4];
            bb[0].f = *(const float2*)&Bs[k][tn * 8 + 0];
            bb[1].f = *(const float2*)&Bs[k][tn * 8 + 2];
            bb[2].f = *(const float2*)&Bs[k][tn * 8 + 4];
            bb[3].f = *(const float2*)&Bs[k][tn * 8 + 6];
#pragma unroll
            for (int i = 0; i < 8; i++) {
                F2 aa; aa.f.x = a[i]; aa.f.y = a[i];
#pragma unroll
                for (int j = 0; j < 4; j++) ffma2(acc[i][j], aa, bb[j]);
            }
        }
    }

#pragma unroll
    for (int i = 0; i < 8; i++) {
        const int row = m0 + tm * 8 + i;
        float* Crow = C + (size_t)row * ldc + n0 + tn * 8;
#pragma unroll
        for (int j = 0; j < 4; j++)
            *(float2*)(Crow + j * 2) = acc[i][j].f;
    }
}

// ============================================================================
// Double softmax with mask:  row <- softmax( softmax(row) * mask ), in place.
// One block (256 threads) per row; row staged in SMEM.
// maskf: float mask source (elementwise !=0), row-major.  Or maskb: byte mask.
// ============================================================================
__device__ __forceinline__ float warp_red_max(float v) {
#pragma unroll
    for (int o = 16; o; o >>= 1) v = fmaxf(v, __shfl_xor_sync(0xffffffffu, v, o));
    return v;
}
__device__ __forceinline__ float warp_red_sum(float v) {
#pragma unroll
    for (int o = 16; o; o >>= 1) v += __shfl_xor_sync(0xffffffffu, v, o);
    return v;
}

template <bool IS_MAX>
__device__ __forceinline__ float block_red(float v, float* red, int t) {
    v = IS_MAX ? warp_red_max(v) : warp_red_sum(v);
    __syncthreads();                       // protect red[] from previous use
    if ((t & 31) == 0) red[t >> 5] = v;
    __syncthreads();
    if (t < 32) {
        float x = (t < 8) ? red[t] : (IS_MAX ? -INFINITY : 0.f);
        x = IS_MAX ? warp_red_max(x) : warp_red_sum(x);
        if (t == 0) red[0] = x;
    }
    __syncthreads();
    return red[0];
}

__global__ void __launch_bounds__(256) softmax2_kernel(
    float* __restrict__ S,
    const float* __restrict__ maskf,
    const unsigned char* __restrict__ maskb)
{
    __shared__ __align__(16) float buf[NDIM];
    __shared__ float red[32];
    const int t = threadIdx.x;
    const int row = blockIdx.x;
    float* Srow = S + (size_t)row * NDIM;

    // pass 1: load + max
    float mx = -INFINITY;
#pragma unroll
    for (int i = t * 4; i < NDIM; i += 1024) {
        float4 v = *(const float4*)(Srow + i);
        *(float4*)&buf[i] = v;
        mx = fmaxf(mx, fmaxf(fmaxf(v.x, v.y), fmaxf(v.z, v.w)));
    }
    const float smax = block_red<true>(mx, red, t);

    // pass 2: exp + sum
    float sum = 0.f;
#pragma unroll
    for (int i = t * 4; i < NDIM; i += 1024) {
        float4 v = *(float4*)&buf[i];
        v.x = __expf(v.x - smax); v.y = __expf(v.y - smax);
        v.z = __expf(v.z - smax); v.w = __expf(v.w - smax);
        *(float4*)&buf[i] = v;
        sum += v.x + v.y + v.z + v.w;
    }
    const float inv = 1.f / block_red<false>(sum, red, t);

    // pass 3: normalize, apply mask, second max
    float mx2 = -INFINITY;
#pragma unroll
    for (int i = t * 4; i < NDIM; i += 1024) {
        float4 v = *(float4*)&buf[i];
        float4 m;
        if (maskf) {
            float4 mm = *(const float4*)(maskf + (size_t)row * NDIM + i);
            m.x = (mm.x != 0.f) ? 1.f : 0.f;
            m.y = (mm.y != 0.f) ? 1.f : 0.f;
            m.z = (mm.z != 0.f) ? 1.f : 0.f;
            m.w = (mm.w != 0.f) ? 1.f : 0.f;
        } else {
            uchar4 mm = *(const uchar4*)(maskb + (size_t)row * NDIM + i);
            m.x = (float)mm.x; m.y = (float)mm.y; m.z = (float)mm.z; m.w = (float)mm.w;
        }
        v.x = v.x * inv * m.x; v.y = v.y * inv * m.y;
        v.z = v.z * inv * m.z; v.w = v.w * inv * m.w;
        *(float4*)&buf[i] = v;
        mx2 = fmaxf(mx2, fmaxf(fmaxf(v.x, v.y), fmaxf(v.z, v.w)));
    }
    const float smax2 = block_red<true>(mx2, red, t);

    // pass 4: second exp + sum
    float sum2 = 0.f;
#pragma unroll
    for (int i = t * 4; i < NDIM; i += 1024) {
        float4 v = *(float4*)&buf[i];
        v.x = __expf(v.x - smax2); v.y = __expf(v.y - smax2);
        v.z = __expf(v.z - smax2); v.w = __expf(v.w - smax2);
        *(float4*)&buf[i] = v;
        sum2 += v.x + v.y + v.z + v.w;
    }
    const float inv2 = 1.f / block_red<false>(sum2, red, t);

    // pass 5: write back
#pragma unroll
    for (int i = t * 4; i < NDIM; i += 1024) {
        float4 v = *(float4*)&buf[i];
        v.x *= inv2; v.y *= inv2; v.z *= inv2; v.w *= inv2;
        *(float4*)(Srow + i) = v;
    }
}

// ============================================================================
// Transposed byte mask:  MT[r][c] = (B[c][r] != 0)   -- coalesced both sides.
// Grid: (128,128), block (32,8).
// ============================================================================
__global__ void mask_transpose_kernel(const float* __restrict__ B,
                                      unsigned char* __restrict__ MT)
{
    __shared__ unsigned char tile[32][33];
    const int bx = blockIdx.x * 32;
    const int by = blockIdx.y * 32;
    const int tx = threadIdx.x;
    const int ty = threadIdx.y;
#pragma unroll
    for (int j = ty; j < 32; j += 8)
        tile[j][tx] = (B[(size_t)(by + j) * NDIM + bx + tx] != 0.f) ? 1 : 0;
    __syncthreads();
#pragma unroll
    for (int j = ty; j < 32; j += 8)
        MT[(size_t)(bx + j) * NDIM + by + tx] = tile[tx][j];
}

// ============================================================================
// launch
// ============================================================================
extern "C" void kernel_launch(void* const* d_in, const int* in_sizes, int n_in,
                              void* d_out, int out_size)
{
    const float* L      = (const float*)d_in[0];
    const float* H      = (const float*)d_in[1];
    const float* B_low  = (const float*)d_in[2];
    const float* H_low  = (const float*)d_in[3];
    const float* B_high = (const float*)d_in[4];
    const float* H_high = (const float*)d_in[5];
    const float* W      = (const float*)d_in[6];
    const float* bvec   = (const float*)d_in[7];
    float* out = (float*)d_out;

    float* S;  float* H4;  unsigned char* MT;
    cudaGetSymbolAddress((void**)&S,  g_S);
    cudaGetSymbolAddress((void**)&H4, g_H4);
    cudaGetSymbolAddress((void**)&MT, g_MT);

    const float scale = 0.03125f;  // 1/sqrt(1024)

    const dim3 gScore(NDIM / BN, NDIM / BM);     // 32 x 32
    const dim3 gOut(DDIM / BN, NDIM / BM);       // 8 x 32
    const dim3 gT(NDIM / 32, NDIM / 32);         // 128 x 128

    // transposed mask for the "low" attention
    mask_transpose_kernel<<<gT, dim3(32, 8)>>>(B_low, MT);

    // --- attention 1: same-order (mask = L != 0) ---
    gemm_nt_kernel<<<gScore, 256>>>(H, DDIM, H, DDIM, S, NDIM, DDIM, scale, nullptr, 0);
    softmax2_kernel<<<NDIM, 256>>>(S, L, nullptr);
    gemm_nn_kernel<<<gOut, 256>>>(S, NDIM, H, DDIM, H4 + 0, 3 * DDIM, NDIM);

    // --- attention 2: lower-order (mask = (B_low != 0)^T) ---
    gemm_nt_kernel<<<gScore, 256>>>(H, DDIM, H_low, DDIM, S, NDIM, DDIM, scale, nullptr, 0);
    softmax2_kernel<<<NDIM, 256>>>(S, nullptr, MT);
    gemm_nn_kernel<<<gOut, 256>>>(S, NDIM, H_low, DDIM, H4 + DDIM, 3 * DDIM, NDIM);

    // --- attention 3: higher-order (mask = B_high != 0) ---
    gemm_nt_kernel<<<gScore, 256>>>(H, DDIM, H_high, DDIM, S, NDIM, DDIM, scale, nullptr, 0);
    softmax2_kernel<<<NDIM, 256>>>(S, B_high, nullptr);
    gemm_nn_kernel<<<gOut, 256>>>(S, NDIM, H_high, DDIM, H4 + 2 * DDIM, 3 * DDIM, NDIM);

    // --- output projection: out = tanh(H4 @ W^T + b) ---
    gemm_nt_kernel<<<gOut, 256>>>(H4, 3 * DDIM, W, 3 * DDIM, out, DDIM, 3 * DDIM,
                                  1.0f, bvec, 1);
}

// round 3
// speedup vs baseline: 2.2350x; 2.2350x over previous
#include <cuda_runtime.h>
#include <cuda_bf16.h>
#include <math.h>
#include <stdint.h>

#define NDIM 4096
#define DDIM 1024

// ---------------- scratch (device globals) ----------------
__device__ float g_S[(size_t)NDIM * NDIM];                       // fp32 scores
__device__ __nv_bfloat16 g_Shi[(size_t)NDIM * NDIM];
__device__ __nv_bfloat16 g_Slo[(size_t)NDIM * NDIM];
__device__ __nv_bfloat16 g_Hhi[3][(size_t)NDIM * DDIM];          // H, H_low, H_high
__device__ __nv_bfloat16 g_Hlo[3][(size_t)NDIM * DDIM];
__device__ __nv_bfloat16 g_HThi[3][(size_t)DDIM * NDIM];         // transposed copies
__device__ __nv_bfloat16 g_HTlo[3][(size_t)DDIM * NDIM];
__device__ __nv_bfloat16 g_H4hi[(size_t)NDIM * 3 * DDIM];
__device__ __nv_bfloat16 g_H4lo[(size_t)NDIM * 3 * DDIM];
__device__ __nv_bfloat16 g_Whi[(size_t)DDIM * 3 * DDIM];
__device__ __nv_bfloat16 g_Wlo[(size_t)DDIM * 3 * DDIM];
__device__ unsigned char g_MT[(size_t)NDIM * NDIM];              // (B_low!=0)^T byte mask

// ---------------- PTX helpers (baseline sm_80-tier only) ----------------
__device__ __forceinline__ uint32_t smem_u32(const void* p) {
    uint32_t a;
    asm("{ .reg .u64 t; cvta.to.shared.u64 t, %1; cvt.u32.u64 %0, t; }" : "=r"(a) : "l"(p));
    return a;
}
__device__ __forceinline__ void cp_async16(uint32_t dst, const void* src) {
    asm volatile("cp.async.cg.shared.global [%0], [%1], 16;" :: "r"(dst), "l"(src) : "memory");
}
__device__ __forceinline__ void cp_commit() {
    asm volatile("cp.async.commit_group;" ::: "memory");
}
template <int N>
__device__ __forceinline__ void cp_wait() {
    asm volatile("cp.async.wait_group %0;" :: "n"(N) : "memory");
}
__device__ __forceinline__ void ldsm4(uint32_t* d, uint32_t addr) {
    asm volatile("ldmatrix.sync.aligned.m8n8.x4.shared.b16 {%0,%1,%2,%3}, [%4];"
        : "=r"(d[0]), "=r"(d[1]), "=r"(d[2]), "=r"(d[3]) : "r"(addr));
}
__device__ __forceinline__ void mma16816(float* c, const uint32_t* a, const uint32_t* b) {
    asm volatile("mma.sync.aligned.m16n8k16.row.col.f32.bf16.bf16.f32 "
        "{%0,%1,%2,%3}, {%4,%5,%6,%7}, {%8,%9}, {%0,%1,%2,%3};"
        : "+f"(c[0]), "+f"(c[1]), "+f"(c[2]), "+f"(c[3])
        : "r"(a[0]), "r"(a[1]), "r"(a[2]), "r"(a[3]), "r"(b[0]), "r"(b[1]));
}

// SMEM tile: 128 rows x 16 bf16 (32B/row), two 16B chunks/row, XOR swizzle.
// phys(r,c) = r*32 + ((c ^ ((r>>2)&1))<<4)   -- conflict-free for ldmatrix & cp.async.
__device__ __forceinline__ uint32_t soff(int r, int c) {
    return (uint32_t)(r * 32 + (((c ^ ((r >> 2) & 1))) << 4));
}

#define BM 128
#define BN 128
#define BKE 16                      // bf16 elements per k-stage
#define OP_BYTES (BM * 32)          // 4096 B per operand per stage
#define STAGE_BYTES (4 * OP_BYTES)  // 16 KB
#define STAGES 3                    // 48 KB total (static smem limit)

// ============================================================================
// HMMA NT GEMM with bf16x2 3-MMA fp32 emulation.
//   C[M,N] = A[M,K] @ B[N,K]^T,  A = A1+A2, B = B1+B2 (hi/lo bf16 splits)
// modes: 0: Cf = alpha*acc   1: Chi/Clo = bf16 split of acc   2: Cf = tanh(acc + bias[n])
// ============================================================================
__global__ void __launch_bounds__(256, 1) gemm_hmma(
    const __nv_bfloat16* __restrict__ A1, const __nv_bfloat16* __restrict__ A2, int lda,
    const __nv_bfloat16* __restrict__ B1, const __nv_bfloat16* __restrict__ B2, int ldb,
    int K, int mode, float alpha,
    float* __restrict__ Cf, __nv_bfloat16* __restrict__ Chi, __nv_bfloat16* __restrict__ Clo,
    int ldc, const float* __restrict__ bias)
{
    __shared__ __align__(128) char sm[STAGES * STAGE_BYTES];

    const int t    = threadIdx.x;
    const int lane = t & 31;
    const int wid  = t >> 5;
    const int wm   = (wid & 3) * 32;   // warp m-offset in CTA tile
    const int wn   = (wid >> 2) * 64;  // warp n-offset in CTA tile
    const int m0   = blockIdx.y * BM;
    const int n0   = blockIdx.x * BN;
    const uint32_t sbase = smem_u32(sm);

    // ------- loader indices: thread t handles row lr, chunk lc of each operand
    const int lr = t >> 1;
    const int lc = t & 1;
    const uint32_t st_off = soff(lr, lc);
    const __nv_bfloat16* gA1 = A1 + (size_t)(m0 + lr) * lda + lc * 8;
    const __nv_bfloat16* gA2 = A2 + (size_t)(m0 + lr) * lda + lc * 8;
    const __nv_bfloat16* gB1 = B1 + (size_t)(n0 + lr) * ldb + lc * 8;
    const __nv_bfloat16* gB2 = B2 + (size_t)(n0 + lr) * ldb + lc * 8;

    // ------- fragment smem offsets (within one operand tile)
    uint32_t adA[2], adB[4];
    {
        const int mm = lane >> 3;
#pragma unroll
        for (int i = 0; i < 2; i++)
            adA[i] = soff(wm + i * 16 + (mm & 1) * 8 + (lane & 7), mm >> 1);
#pragma unroll
        for (int j = 0; j < 4; j++)
            adB[j] = soff(wn + j * 16 + (mm >> 1) * 8 + (lane & 7), mm & 1);
    }

    float acc[2][8][4];
#pragma unroll
    for (int i = 0; i < 2; i++)
#pragma unroll
        for (int j = 0; j < 8; j++)
#pragma unroll
            for (int q = 0; q < 4; q++) acc[i][j][q] = 0.f;

    const int T = K / BKE;

    // ------- prologue: fill pipeline
#pragma unroll
    for (int s = 0; s < STAGES; s++) {
        const uint32_t d = sbase + s * STAGE_BYTES + st_off;
        const int k = s * BKE;
        cp_async16(d,                gA1 + k);
        cp_async16(d + OP_BYTES,     gA2 + k);
        cp_async16(d + 2 * OP_BYTES, gB1 + k);
        cp_async16(d + 3 * OP_BYTES, gB2 + k);
        cp_commit();
    }

    int sidx = 0;
    for (int tt = 0; tt < T; tt++) {
        cp_wait<STAGES - 1>();
        __syncthreads();

        const uint32_t sb = sbase + sidx * STAGE_BYTES;
        uint32_t a1[2][4], a2[2][4], b1[8][2], b2[8][2];
#pragma unroll
        for (int i = 0; i < 2; i++) {
            ldsm4(a1[i], sb + adA[i]);
            ldsm4(a2[i], sb + OP_BYTES + adA[i]);
        }
#pragma unroll
        for (int j = 0; j < 4; j++) {
            uint32_t tmp[4];
            ldsm4(tmp, sb + 2 * OP_BYTES + adB[j]);
            b1[2*j][0] = tmp[0]; b1[2*j][1] = tmp[1];
            b1[2*j+1][0] = tmp[2]; b1[2*j+1][1] = tmp[3];
            ldsm4(tmp, sb + 3 * OP_BYTES + adB[j]);
            b2[2*j][0] = tmp[0]; b2[2*j][1] = tmp[1];
            b2[2*j+1][0] = tmp[2]; b2[2*j+1][1] = tmp[3];
        }
#pragma unroll
        for (int i = 0; i < 2; i++)
#pragma unroll
            for (int j = 0; j < 8; j++) {
                mma16816(acc[i][j], a1[i], b1[j]);
                mma16816(acc[i][j], a1[i], b2[j]);
                mma16816(acc[i][j], a2[i], b1[j]);
            }

        __syncthreads();   // everyone done reading this stage before overwrite
        if (tt + STAGES < T) {
            const uint32_t d = sbase + sidx * STAGE_BYTES + st_off;
            const int k = (tt + STAGES) * BKE;
            cp_async16(d,                gA1 + k);
            cp_async16(d + OP_BYTES,     gA2 + k);
            cp_async16(d + 2 * OP_BYTES, gB1 + k);
            cp_async16(d + 3 * OP_BYTES, gB2 + k);
        }
        cp_commit();
        sidx = (sidx + 1) % STAGES;
    }

    // ------- epilogue
    const int row0 = m0 + wm + (lane >> 2);
    const int colb = n0 + wn + (lane & 3) * 2;
#pragma unroll
    for (int i = 0; i < 2; i++) {
#pragma unroll
        for (int j = 0; j < 8; j++) {
            const int r0 = row0 + i * 16;
            const int r1 = r0 + 8;
            const int col = colb + j * 8;
            const float* c = acc[i][j];
            if (mode == 0) {
                float2 v0 = make_float2(c[0] * alpha, c[1] * alpha);
                float2 v1 = make_float2(c[2] * alpha, c[3] * alpha);
                *(float2*)(Cf + (size_t)r0 * ldc + col) = v0;
                *(float2*)(Cf + (size_t)r1 * ldc + col) = v1;
            } else if (mode == 1) {
                __nv_bfloat16 h0 = __float2bfloat16(c[0]);
                __nv_bfloat16 h1 = __float2bfloat16(c[1]);
                __nv_bfloat16 h2 = __float2bfloat16(c[2]);
                __nv_bfloat16 h3 = __float2bfloat16(c[3]);
                __nv_bfloat162 hh0; hh0.x = h0; hh0.y = h1;
                __nv_bfloat162 hh1; hh1.x = h2; hh1.y = h3;
                __nv_bfloat162 ll0, ll1;
                ll0.x = __float2bfloat16(c[0] - __bfloat162float(h0));
                ll0.y = __float2bfloat16(c[1] - __bfloat162float(h1));
                ll1.x = __float2bfloat16(c[2] - __bfloat162float(h2));
                ll1.y = __float2bfloat16(c[3] - __bfloat162float(h3));
                *(__nv_bfloat162*)(Chi + (size_t)r0 * ldc + col) = hh0;
                *(__nv_bfloat162*)(Clo + (size_t)r0 * ldc + col) = ll0;
                *(__nv_bfloat162*)(Chi + (size_t)r1 * ldc + col) = hh1;
                *(__nv_bfloat162*)(Clo + (size_t)r1 * ldc + col) = ll1;
            } else {
                float2 v0 = make_float2(tanhf(c[0] + bias[col]), tanhf(c[1] + bias[col + 1]));
                float2 v1 = make_float2(tanhf(c[2] + bias[col]), tanhf(c[3] + bias[col + 1]));
                *(float2*)(Cf + (size_t)r0 * ldc + col) = v0;
                *(float2*)(Cf + (size_t)r1 * ldc + col) = v1;
            }
        }
    }
}

// ============================================================================
// fp32 -> bf16 hi/lo split (elementwise)
// ============================================================================
__global__ void split_kernel(const float* __restrict__ X,
                             __nv_bfloat16* __restrict__ hi,
                             __nv_bfloat16* __restrict__ lo, int count)
{
    int i = (blockIdx.x * blockDim.x + threadIdx.x) * 4;
    if (i >= count) return;
    float4 v = *(const float4*)(X + i);
    __nv_bfloat16 h0 = __float2bfloat16(v.x), h1 = __float2bfloat16(v.y);
    __nv_bfloat16 h2 = __float2bfloat16(v.z), h3 = __float2bfloat16(v.w);
    __nv_bfloat162 a; a.x = h0; a.y = h1;
    __nv_bfloat162 b; b.x = h2; b.y = h3;
    __nv_bfloat162 c; c.x = __float2bfloat16(v.x - __bfloat162float(h0));
    c.y = __float2bfloat16(v.y - __bfloat162float(h1));
    __nv_bfloat162 d; d.x = __float2bfloat16(v.z - __bfloat162float(h2));
    d.y = __float2bfloat16(v.w - __bfloat162float(h3));
    *(__nv_bfloat162*)(hi + i)     = a;
    *(__nv_bfloat162*)(hi + i + 2) = b;
    *(__nv_bfloat162*)(lo + i)     = c;
    *(__nv_bfloat162*)(lo + i + 2) = d;
}

// ============================================================================
// fp32 [R x C] -> transposed bf16 hi/lo [C x R]
// ============================================================================
__global__ void split_t_kernel(const float* __restrict__ X, int R, int C,
                               __nv_bfloat16* __restrict__ hiT,
                               __nv_bfloat16* __restrict__ loT)
{
    __shared__ float tile[32][33];
    const int c0 = blockIdx.x * 32;
    const int r0 = blockIdx.y * 32;
    const int tx = threadIdx.x;
    const int ty = threadIdx.y;
#pragma unroll
    for (int j = ty; j < 32; j += 8)
        tile[j][tx] = X[(size_t)(r0 + j) * C + c0 + tx];
    __syncthreads();
#pragma unroll
    for (int j = ty; j < 32; j += 8) {
        float v = tile[tx][j];
        __nv_bfloat16 h = __float2bfloat16(v);
        __nv_bfloat16 l = __float2bfloat16(v - __bfloat162float(h));
        hiT[(size_t)(c0 + j) * R + r0 + tx] = h;
        loT[(size_t)(c0 + j) * R + r0 + tx] = l;
    }
}

// ============================================================================
// double softmax with mask; reads fp32 S, writes bf16 hi/lo splits of result
// ============================================================================
__device__ __forceinline__ float warp_red_max(float v) {
#pragma unroll
    for (int o = 16; o; o >>= 1) v = fmaxf(v, __shfl_xor_sync(0xffffffffu, v, o));
    return v;
}
__device__ __forceinline__ float warp_red_sum(float v) {
#pragma unroll
    for (int o = 16; o; o >>= 1) v += __shfl_xor_sync(0xffffffffu, v, o);
    return v;
}
template <bool IS_MAX>
__device__ __forceinline__ float block_red(float v, float* red, int t) {
    v = IS_MAX ? warp_red_max(v) : warp_red_sum(v);
    __syncthreads();
    if ((t & 31) == 0) red[t >> 5] = v;
    __syncthreads();
    if (t < 32) {
        float x = (t < 8) ? red[t] : (IS_MAX ? -INFINITY : 0.f);
        x = IS_MAX ? warp_red_max(x) : warp_red_sum(x);
        if (t == 0) red[0] = x;
    }
    __syncthreads();
    return red[0];
}

__global__ void __launch_bounds__(256) softmax2_kernel(
    const float* __restrict__ S,
    const float* __restrict__ maskf,
    const unsigned char* __restrict__ maskb,
    __nv_bfloat16* __restrict__ Phi,
    __nv_bfloat16* __restrict__ Plo)
{
    __shared__ __align__(16) float buf[NDIM];
    __shared__ float red[32];
    const int t = threadIdx.x;
    const int row = blockIdx.x;
    const float* Srow = S + (size_t)row * NDIM;

    float mx = -INFINITY;
#pragma unroll
    for (int i = t * 4; i < NDIM; i += 1024) {
        float4 v = *(const float4*)(Srow + i);
        *(float4*)&buf[i] = v;
        mx = fmaxf(mx, fmaxf(fmaxf(v.x, v.y), fmaxf(v.z, v.w)));
    }
    const float smax = block_red<true>(mx, red, t);

    float sum = 0.f;
#pragma unroll
    for (int i = t * 4; i < NDIM; i += 1024) {
        float4 v = *(float4*)&buf[i];
        v.x = __expf(v.x - smax); v.y = __expf(v.y - smax);
        v.z = __expf(v.z - smax); v.w = __expf(v.w - smax);
        *(float4*)&buf[i] = v;
        sum += v.x + v.y + v.z + v.w;
    }
    const float inv = 1.f / block_red<false>(sum, red, t);

    float mx2 = -INFINITY;
#pragma unroll
    for (int i = t * 4; i < NDIM; i += 1024) {
        float4 v = *(float4*)&buf[i];
        float4 m;
        if (maskf) {
            float4 mm = *(const float4*)(maskf + (size_t)row * NDIM + i);
            m.x = (mm.x != 0.f) ? 1.f : 0.f;
            m.y = (mm.y != 0.f) ? 1.f : 0.f;
            m.z = (mm.z != 0.f) ? 1.f : 0.f;
            m.w = (mm.w != 0.f) ? 1.f : 0.f;
        } else {
            uchar4 mm = *(const uchar4*)(maskb + (size_t)row * NDIM + i);
            m.x = (float)mm.x; m.y = (float)mm.y; m.z = (float)mm.z; m.w = (float)mm.w;
        }
        v.x = v.x * inv * m.x; v.y = v.y * inv * m.y;
        v.z = v.z * inv * m.z; v.w = v.w * inv * m.w;
        *(float4*)&buf[i] = v;
        mx2 = fmaxf(mx2, fmaxf(fmaxf(v.x, v.y), fmaxf(v.z, v.w)));
    }
    const float smax2 = block_red<true>(mx2, red, t);

    float sum2 = 0.f;
#pragma unroll
    for (int i = t * 4; i < NDIM; i += 1024) {
        float4 v = *(float4*)&buf[i];
        v.x = __expf(v.x - smax2); v.y = __expf(v.y - smax2);
        v.z = __expf(v.z - smax2); v.w = __expf(v.w - smax2);
        *(float4*)&buf[i] = v;
        sum2 += v.x + v.y + v.z + v.w;
    }
    const float inv2 = 1.f / block_red<false>(sum2, red, t);

    __nv_bfloat16* hrow = Phi + (size_t)row * NDIM;
    __nv_bfloat16* lrow = Plo + (size_t)row * NDIM;
#pragma unroll
    for (int i = t * 4; i < NDIM; i += 1024) {
        float4 v = *(float4*)&buf[i];
        v.x *= inv2; v.y *= inv2; v.z *= inv2; v.w *= inv2;
        __nv_bfloat16 h0 = __float2bfloat16(v.x), h1 = __float2bfloat16(v.y);
        __nv_bfloat16 h2 = __float2bfloat16(v.z), h3 = __float2bfloat16(v.w);
        __nv_bfloat162 a; a.x = h0; a.y = h1;
        __nv_bfloat162 b; b.x = h2; b.y = h3;
        __nv_bfloat162 c; c.x = __float2bfloat16(v.x - __bfloat162float(h0));
        c.y = __float2bfloat16(v.y - __bfloat162float(h1));
        __nv_bfloat162 d; d.x = __float2bfloat16(v.z - __bfloat162float(h2));
        d.y = __float2bfloat16(v.w - __bfloat162float(h3));
        *(__nv_bfloat162*)(hrow + i)     = a;
        *(__nv_bfloat162*)(hrow + i + 2) = b;
        *(__nv_bfloat162*)(lrow + i)     = c;
        *(__nv_bfloat162*)(lrow + i + 2) = d;
    }
}

// ============================================================================
// transposed byte mask: MT[r][c] = (B[c][r] != 0)
// ============================================================================
__global__ void mask_transpose_kernel(const float* __restrict__ B,
                                      unsigned char* __restrict__ MT)
{
    __shared__ unsigned char tile[32][33];
    const int bx = blockIdx.x * 32;
    const int by = blockIdx.y * 32;
    const int tx = threadIdx.x;
    const int ty = threadIdx.y;
#pragma unroll
    for (int j = ty; j < 32; j += 8)
        tile[j][tx] = (B[(size_t)(by + j) * NDIM + bx + tx] != 0.f) ? 1 : 0;
    __syncthreads();
#pragma unroll
    for (int j = ty; j < 32; j += 8)
        MT[(size_t)(bx + j) * NDIM + by + tx] = tile[tx][j];
}

// ============================================================================
// launch
// ============================================================================
extern "C" void kernel_launch(void* const* d_in, const int* in_sizes, int n_in,
                              void* d_out, int out_size)
{
    const float* L      = (const float*)d_in[0];
    const float* H      = (const float*)d_in[1];
    const float* B_low  = (const float*)d_in[2];
    const float* H_low  = (const float*)d_in[3];
    const float* B_high = (const float*)d_in[4];
    const float* H_high = (const float*)d_in[5];
    const float* W      = (const float*)d_in[6];
    const float* bvec   = (const float*)d_in[7];
    float* out = (float*)d_out;

    float* S;
    __nv_bfloat16 *Shi, *Slo, *Hhi, *Hlo, *HThi, *HTlo, *H4hi, *H4lo, *Whi, *Wlo;
    unsigned char* MT;
    cudaGetSymbolAddress((void**)&S,    g_S);
    cudaGetSymbolAddress((void**)&Shi,  g_Shi);
    cudaGetSymbolAddress((void**)&Slo,  g_Slo);
    cudaGetSymbolAddress((void**)&Hhi,  g_Hhi);
    cudaGetSymbolAddress((void**)&Hlo,  g_Hlo);
    cudaGetSymbolAddress((void**)&HThi, g_HThi);
    cudaGetSymbolAddress((void**)&HTlo, g_HTlo);
    cudaGetSymbolAddress((void**)&H4hi, g_H4hi);
    cudaGetSymbolAddress((void**)&H4lo, g_H4lo);
    cudaGetSymbolAddress((void**)&Whi,  g_Whi);
    cudaGetSymbolAddress((void**)&Wlo,  g_Wlo);
    cudaGetSymbolAddress((void**)&MT,   g_MT);

    const size_t HSZ = (size_t)NDIM * DDIM;
    const float* Hsrc[3] = {H, H_low, H_high};

    const int splitThreads = 256;
    const int hBlocks = (int)(HSZ / 4 / splitThreads);

    for (int j = 0; j < 3; j++) {
        split_kernel<<<hBlocks, splitThreads>>>(Hsrc[j], Hhi + j * HSZ, Hlo + j * HSZ, (int)HSZ);
        split_t_kernel<<<dim3(DDIM / 32, NDIM / 32), dim3(32, 8)>>>(
            Hsrc[j], NDIM, DDIM, HThi + j * HSZ, HTlo + j * HSZ);
    }
    split_kernel<<<(int)((size_t)DDIM * 3 * DDIM / 4 / splitThreads), splitThreads>>>(
        W, Whi, Wlo, (int)((size_t)DDIM * 3 * DDIM));
    mask_transpose_kernel<<<dim3(NDIM / 32, NDIM / 32), dim3(32, 8)>>>(B_low, MT);

    const float scale = 0.03125f;  // 1/sqrt(1024)
    const dim3 gScore(NDIM / BN, NDIM / BM);   // 32 x 32
    const dim3 gOut(DDIM / BN, NDIM / BM);     // 8 x 32

    const float* masks_f[3] = {L, nullptr, B_high};

    for (int j = 0; j < 3; j++) {
        // scores: S = scale * Hq @ Hkv^T
        gemm_hmma<<<gScore, 256>>>(
            Hhi, Hlo, DDIM, Hhi + j * HSZ, Hlo + j * HSZ, DDIM,
            DDIM, 0, scale, S, nullptr, nullptr, NDIM, nullptr);
        // double softmax + mask -> bf16 split probabilities
        softmax2_kernel<<<NDIM, 256>>>(S, masks_f[j], j == 1 ? MT : nullptr, Shi, Slo);
        // AV: H4[:, j*D:(j+1)*D] = P @ KV   (B operand = KV^T, K-major)
        gemm_hmma<<<gOut, 256>>>(
            Shi, Slo, NDIM, HThi + j * HSZ, HTlo + j * HSZ, NDIM,
            NDIM, 1, 1.0f, nullptr, H4hi + j * DDIM, H4lo + j * DDIM, 3 * DDIM, nullptr);
    }

    // out = tanh(H4 @ W^T + b)
    gemm_hmma<<<gOut, 256>>>(
        H4hi, H4lo, 3 * DDIM, Whi, Wlo, 3 * DDIM,
        3 * DDIM, 2, 1.0f, out, nullptr, nullptr, DDIM, bvec);
}

// round 4
// speedup vs baseline: 3.6133x; 1.6167x over previous
#include <cuda_runtime.h>
#include <cuda_fp16.h>
#include <math.h>
#include <stdint.h>

#define NDIM 4096
#define DDIM 1024

// ---------------- scratch (device globals) ----------------
__device__ float g_S[(size_t)NDIM * NDIM];                 // fp32 scores
__device__ __half g_Shi[(size_t)NDIM * NDIM];              // P hi
__device__ __half g_Slo[(size_t)NDIM * NDIM];              // P lo
__device__ __half g_Hhi[3][(size_t)NDIM * DDIM];           // fp16(H / H_low / H_high)
__device__ __half g_Hlo[(size_t)NDIM * DDIM];              // lo residual of H only (A operand)
__device__ __half g_HT[3][(size_t)DDIM * NDIM];            // fp16 transposed KV
__device__ __half g_H4hi[(size_t)NDIM * 3 * DDIM];
__device__ __half g_H4lo[(size_t)NDIM * 3 * DDIM];
__device__ __half g_Wh[(size_t)DDIM * 3 * DDIM];           // fp16(W)
__device__ unsigned char g_MT[(size_t)NDIM * NDIM];        // (B_low!=0)^T byte mask

// ---------------- PTX helpers (baseline tier: compiles under sm_103) --------
__device__ __forceinline__ uint32_t smem_u32(const void* p) {
    uint32_t a;
    asm("{ .reg .u64 t; cvta.to.shared.u64 t, %1; cvt.u32.u64 %0, t; }" : "=r"(a) : "l"(p));
    return a;
}
__device__ __forceinline__ void cp_async16(uint32_t dst, const void* src) {
    asm volatile("cp.async.cg.shared.global [%0], [%1], 16;" :: "r"(dst), "l"(src) : "memory");
}
__device__ __forceinline__ void cp_commit() {
    asm volatile("cp.async.commit_group;" ::: "memory");
}
template <int N>
__device__ __forceinline__ void cp_wait() {
    asm volatile("cp.async.wait_group %0;" :: "n"(N) : "memory");
}
__device__ __forceinline__ void ldsm4(uint32_t* d, uint32_t addr) {
    asm volatile("ldmatrix.sync.aligned.m8n8.x4.shared.b16 {%0,%1,%2,%3}, [%4];"
        : "=r"(d[0]), "=r"(d[1]), "=r"(d[2]), "=r"(d[3]) : "r"(addr));
}
__device__ __forceinline__ void mma16816(float* c, const uint32_t* a, const uint32_t* b) {
    asm volatile("mma.sync.aligned.m16n8k16.row.col.f32.f16.f16.f32 "
        "{%0,%1,%2,%3}, {%4,%5,%6,%7}, {%8,%9}, {%0,%1,%2,%3};"
        : "+f"(c[0]), "+f"(c[1]), "+f"(c[2]), "+f"(c[3])
        : "r"(a[0]), "r"(a[1]), "r"(a[2]), "r"(a[3]), "r"(b[0]), "r"(b[1]));
}

// SMEM tile: 128 rows x 16 fp16 (32B/row), two 16B chunks/row, XOR swizzle.
__device__ __forceinline__ uint32_t soff(int r, int c) {
    return (uint32_t)(r * 32 + (((c ^ ((r >> 2) & 1))) << 4));
}

#define BM 128
#define BN 128
#define BKE 16                      // fp16 elements per k-stage
#define OPB (BM * 32)               // 4096 B per operand per stage
#define STB (3 * OPB)               // 12 KB per stage (A1, A2, B)
#define STAGES 4                    // 48 KB total (static smem limit, exact)

// ============================================================================
// HMMA NT GEMM, fp16 2-pass fp32 emulation:
//   C[M,N] = (A1+A2)[M,K] @ B[N,K]^T ;  A1/A2 = fp16 hi/lo split, B = fp16 round
// modes: 0: Cf = alpha*acc   1: Chi/Clo = fp16 split of acc   2: Cf = tanh(acc + bias[n])
// ============================================================================
__global__ void __launch_bounds__(256, 2) gemm_hmma(
    const __half* __restrict__ A1, const __half* __restrict__ A2, int lda,
    const __half* __restrict__ B, int ldb,
    int K, int mode, float alpha,
    float* __restrict__ Cf, __half* __restrict__ Chi, __half* __restrict__ Clo,
    int ldc, const float* __restrict__ bias)
{
    __shared__ __align__(128) char sm[STAGES * STB];

    const int t    = threadIdx.x;
    const int lane = t & 31;
    const int wid  = t >> 5;
    const int wm   = (wid & 3) * 32;   // warp m-offset
    const int wn   = (wid >> 2) * 64;  // warp n-offset
    const int m0   = blockIdx.y * BM;
    const int n0   = blockIdx.x * BN;
    const uint32_t sbase = smem_u32(sm);

    // loader: thread t -> row lr, 16B chunk lc of each operand
    const int lr = t >> 1;
    const int lc = t & 1;
    const uint32_t st_off = soff(lr, lc);
    const __half* gA1 = A1 + (size_t)(m0 + lr) * lda + lc * 8;
    const __half* gA2 = A2 + (size_t)(m0 + lr) * lda + lc * 8;
    const __half* gB  = B  + (size_t)(n0 + lr) * ldb + lc * 8;

    // fragment smem offsets
    uint32_t adA[2], adB[4];
    {
        const int mm = lane >> 3;
#pragma unroll
        for (int i = 0; i < 2; i++)
            adA[i] = soff(wm + i * 16 + (mm & 1) * 8 + (lane & 7), mm >> 1);
#pragma unroll
        for (int j = 0; j < 4; j++)
            adB[j] = soff(wn + j * 16 + (mm >> 1) * 8 + (lane & 7), mm & 1);
    }

    float acc[2][8][4];
#pragma unroll
    for (int i = 0; i < 2; i++)
#pragma unroll
        for (int j = 0; j < 8; j++)
#pragma unroll
            for (int q = 0; q < 4; q++) acc[i][j][q] = 0.f;

    const int T = K / BKE;

    // prologue: stage tiles 0..STAGES-2 (one commit group per tile)
#pragma unroll
    for (int s = 0; s < STAGES - 1; s++) {
        const uint32_t d = sbase + s * STB + st_off;
        const int k = s * BKE;
        cp_async16(d,            gA1 + k);
        cp_async16(d + OPB,      gA2 + k);
        cp_async16(d + 2 * OPB,  gB  + k);
        cp_commit();
    }

    for (int tt = 0; tt < T; tt++) {
        __syncthreads();   // all warps done reading buffer (tt-1)%STAGES
        const int nt = tt + STAGES - 1;
        if (nt < T) {
            const uint32_t d = sbase + (nt % STAGES) * STB + st_off;
            const int k = nt * BKE;
            cp_async16(d,            gA1 + k);
            cp_async16(d + OPB,      gA2 + k);
            cp_async16(d + 2 * OPB,  gB  + k);
        }
        cp_commit();
        cp_wait<STAGES - 2>();   // tile tt (group tt) complete
        __syncthreads();

        const uint32_t sb = sbase + (tt % STAGES) * STB;
        uint32_t a1[2][4], a2[2][4], b[8][2];
#pragma unroll
        for (int i = 0; i < 2; i++) {
            ldsm4(a1[i], sb + adA[i]);
            ldsm4(a2[i], sb + OPB + adA[i]);
        }
#pragma unroll
        for (int j = 0; j < 4; j++) {
            uint32_t tmp[4];
            ldsm4(tmp, sb + 2 * OPB + adB[j]);
            b[2*j][0]   = tmp[0]; b[2*j][1]   = tmp[1];
            b[2*j+1][0] = tmp[2]; b[2*j+1][1] = tmp[3];
        }
#pragma unroll
        for (int i = 0; i < 2; i++)
#pragma unroll
            for (int j = 0; j < 8; j++) {
                mma16816(acc[i][j], a1[i], b[j]);
                mma16816(acc[i][j], a2[i], b[j]);
            }
    }

    // epilogue
    const int row0 = m0 + wm + (lane >> 2);
    const int colb = n0 + wn + (lane & 3) * 2;
#pragma unroll
    for (int i = 0; i < 2; i++) {
#pragma unroll
        for (int j = 0; j < 8; j++) {
            const int r0 = row0 + i * 16;
            const int r1 = r0 + 8;
            const int col = colb + j * 8;
            const float* c = acc[i][j];
            if (mode == 0) {
                *(float2*)(Cf + (size_t)r0 * ldc + col) = make_float2(c[0] * alpha, c[1] * alpha);
                *(float2*)(Cf + (size_t)r1 * ldc + col) = make_float2(c[2] * alpha, c[3] * alpha);
            } else if (mode == 1) {
                __half h0 = __float2half_rn(c[0]);
                __half h1 = __float2half_rn(c[1]);
                __half h2 = __float2half_rn(c[2]);
                __half h3 = __float2half_rn(c[3]);
                __half2 hh0; hh0.x = h0; hh0.y = h1;
                __half2 hh1; hh1.x = h2; hh1.y = h3;
                __half2 ll0, ll1;
                ll0.x = __float2half_rn(c[0] - __half2float(h0));
                ll0.y = __float2half_rn(c[1] - __half2float(h1));
                ll1.x = __float2half_rn(c[2] - __half2float(h2));
                ll1.y = __float2half_rn(c[3] - __half2float(h3));
                *(__half2*)(Chi + (size_t)r0 * ldc + col) = hh0;
                *(__half2*)(Clo + (size_t)r0 * ldc + col) = ll0;
                *(__half2*)(Chi + (size_t)r1 * ldc + col) = hh1;
                *(__half2*)(Clo + (size_t)r1 * ldc + col) = ll1;
            } else {
                *(float2*)(Cf + (size_t)r0 * ldc + col) =
                    make_float2(tanhf(c[0] + bias[col]), tanhf(c[1] + bias[col + 1]));
                *(float2*)(Cf + (size_t)r1 * ldc + col) =
                    make_float2(tanhf(c[2] + bias[col]), tanhf(c[3] + bias[col + 1]));
            }
        }
    }
}

// ============================================================================
// fp32 -> fp16 hi (+ optional lo residual), elementwise
// ============================================================================
__global__ void split_kernel(const float* __restrict__ X,
                             __half* __restrict__ hi,
                             __half* __restrict__ lo, int count)
{
    int i = (blockIdx.x * blockDim.x + threadIdx.x) * 4;
    if (i >= count) return;
    float4 v = *(const float4*)(X + i);
    __half h0 = __float2half_rn(v.x), h1 = __float2half_rn(v.y);
    __half h2 = __float2half_rn(v.z), h3 = __float2half_rn(v.w);
    __half2 a; a.x = h0; a.y = h1;
    __half2 b; b.x = h2; b.y = h3;
    *(__half2*)(hi + i)     = a;
    *(__half2*)(hi + i + 2) = b;
    if (lo) {
        __half2 c; c.x = __float2half_rn(v.x - __half2float(h0));
        c.y = __float2half_rn(v.y - __half2float(h1));
        __half2 d; d.x = __float2half_rn(v.z - __half2float(h2));
        d.y = __float2half_rn(v.w - __half2float(h3));
        *(__half2*)(lo + i)     = c;
        *(__half2*)(lo + i + 2) = d;
    }
}

// ============================================================================
// fp32 [R x C] -> transposed fp16 [C x R]  (round only)
// ============================================================================
__global__ void round_t_kernel(const float* __restrict__ X, int R, int C,
                               __half* __restrict__ hT)
{
    __shared__ float tile[32][33];
    const int c0 = blockIdx.x * 32;
    const int r0 = blockIdx.y * 32;
    const int tx = threadIdx.x;
    const int ty = threadIdx.y;
#pragma unroll
    for (int j = ty; j < 32; j += 8)
        tile[j][tx] = X[(size_t)(r0 + j) * C + c0 + tx];
    __syncthreads();
#pragma unroll
    for (int j = ty; j < 32; j += 8)
        hT[(size_t)(c0 + j) * R + r0 + tx] = __float2half_rn(tile[tx][j]);
}

// ============================================================================
// double softmax with mask; reads fp32 S, writes fp16 hi/lo splits of result
// ============================================================================
__device__ __forceinline__ float warp_red_max(float v) {
#pragma unroll
    for (int o = 16; o; o >>= 1) v = fmaxf(v, __shfl_xor_sync(0xffffffffu, v, o));
    return v;
}
__device__ __forceinline__ float warp_red_sum(float v) {
#pragma unroll
    for (int o = 16; o; o >>= 1) v += __shfl_xor_sync(0xffffffffu, v, o);
    return v;
}
template <bool IS_MAX>
__device__ __forceinline__ float block_red(float v, float* red, int t) {
    v = IS_MAX ? warp_red_max(v) : warp_red_sum(v);
    __syncthreads();
    if ((t & 31) == 0) red[t >> 5] = v;
    __syncthreads();
    if (t < 32) {
        float x = (t < 8) ? red[t] : (IS_MAX ? -INFINITY : 0.f);
        x = IS_MAX ? warp_red_max(x) : warp_red_sum(x);
        if (t == 0) red[0] = x;
    }
    __syncthreads();
    return red[0];
}

__global__ void __launch_bounds__(256) softmax2_kernel(
    const float* __restrict__ S,
    const float* __restrict__ maskf,
    const unsigned char* __restrict__ maskb,
    __half* __restrict__ Phi,
    __half* __restrict__ Plo)
{
    __shared__ __align__(16) float buf[NDIM];
    __shared__ float red[32];
    const int t = threadIdx.x;
    const int row = blockIdx.x;
    const float* Srow = S + (size_t)row * NDIM;

    float mx = -INFINITY;
#pragma unroll
    for (int i = t * 4; i < NDIM; i += 1024) {
        float4 v = *(const float4*)(Srow + i);
        *(float4*)&buf[i] = v;
        mx = fmaxf(mx, fmaxf(fmaxf(v.x, v.y), fmaxf(v.z, v.w)));
    }
    const float smax = block_red<true>(mx, red, t);

    float sum = 0.f;
#pragma unroll
    for (int i = t * 4; i < NDIM; i += 1024) {
        float4 v = *(float4*)&buf[i];
        v.x = __expf(v.x - smax); v.y = __expf(v.y - smax);
        v.z = __expf(v.z - smax); v.w = __expf(v.w - smax);
        *(float4*)&buf[i] = v;
        sum += v.x + v.y + v.z + v.w;
    }
    const float inv = 1.f / block_red<false>(sum, red, t);

    float mx2 = -INFINITY;
#pragma unroll
    for (int i = t * 4; i < NDIM; i += 1024) {
        float4 v = *(float4*)&buf[i];
        float4 m;
        if (maskf) {
            float4 mm = *(const float4*)(maskf + (size_t)row * NDIM + i);
            m.x = (mm.x != 0.f) ? 1.f : 0.f;
            m.y = (mm.y != 0.f) ? 1.f : 0.f;
            m.z = (mm.z != 0.f) ? 1.f : 0.f;
            m.w = (mm.w != 0.f) ? 1.f : 0.f;
        } else {
            uchar4 mm = *(const uchar4*)(maskb + (size_t)row * NDIM + i);
            m.x = (float)mm.x; m.y = (float)mm.y; m.z = (float)mm.z; m.w = (float)mm.w;
        }
        v.x = v.x * inv * m.x; v.y = v.y * inv * m.y;
        v.z = v.z * inv * m.z; v.w = v.w * inv * m.w;
        *(float4*)&buf[i] = v;
        mx2 = fmaxf(mx2, fmaxf(fmaxf(v.x, v.y), fmaxf(v.z, v.w)));
    }
    const float smax2 = block_red<true>(mx2, red, t);

    float sum2 = 0.f;
#pragma unroll
    for (int i = t * 4; i < NDIM; i += 1024) {
        float4 v = *(float4*)&buf[i];
        v.x = __expf(v.x - smax2); v.y = __expf(v.y - smax2);
        v.z = __expf(v.z - smax2); v.w = __expf(v.w - smax2);
        *(float4*)&buf[i] = v;
        sum2 += v.x + v.y + v.z + v.w;
    }
    const float inv2 = 1.f / block_red<false>(sum2, red, t);

    __half* hrow = Phi + (size_t)row * NDIM;
    __half* lrow = Plo + (size_t)row * NDIM;
#pragma unroll
    for (int i = t * 4; i < NDIM; i += 1024) {
        float4 v = *(float4*)&buf[i];
        v.x *= inv2; v.y *= inv2; v.z *= inv2; v.w *= inv2;
        __half h0 = __float2half_rn(v.x), h1 = __float2half_rn(v.y);
        __half h2 = __float2half_rn(v.z), h3 = __float2half_rn(v.w);
        __half2 a; a.x = h0; a.y = h1;
        __half2 b; b.x = h2; b.y = h3;
        __half2 c; c.x = __float2half_rn(v.x - __half2float(h0));
        c.y = __float2half_rn(v.y - __half2float(h1));
        __half2 d; d.x = __float2half_rn(v.z - __half2float(h2));
        d.y = __float2half_rn(v.w - __half2float(h3));
        *(__half2*)(hrow + i)     = a;
        *(__half2*)(hrow + i + 2) = b;
        *(__half2*)(lrow + i)     = c;
        *(__half2*)(lrow + i + 2) = d;
    }
}

// ============================================================================
// transposed byte mask: MT[r][c] = (B[c][r] != 0)
// ============================================================================
__global__ void mask_transpose_kernel(const float* __restrict__ B,
                                      unsigned char* __restrict__ MT)
{
    __shared__ unsigned char tile[32][33];
    const int bx = blockIdx.x * 32;
    const int by = blockIdx.y * 32;
    const int tx = threadIdx.x;
    const int ty = threadIdx.y;
#pragma unroll
    for (int j = ty; j < 32; j += 8)
        tile[j][tx] = (B[(size_t)(by + j) * NDIM + bx + tx] != 0.f) ? 1 : 0;
    __syncthreads();
#pragma unroll
    for (int j = ty; j < 32; j += 8)
        MT[(size_t)(bx + j) * NDIM + by + tx] = tile[tx][j];
}

// ============================================================================
// launch
// ============================================================================
extern "C" void kernel_launch(void* const* d_in, const int* in_sizes, int n_in,
                              void* d_out, int out_size)
{
    const float* L      = (const float*)d_in[0];
    const float* H      = (const float*)d_in[1];
    const float* B_low  = (const float*)d_in[2];
    const float* H_low  = (const float*)d_in[3];
    const float* B_high = (const float*)d_in[4];
    const float* H_high = (const float*)d_in[5];
    const float* W      = (const float*)d_in[6];
    const float* bvec   = (const float*)d_in[7];
    float* out = (float*)d_out;

    float* S;
    __half *Shi, *Slo, *Hhi, *Hlo, *HT, *H4hi, *H4lo, *Wh;
    unsigned char* MT;
    cudaGetSymbolAddress((void**)&S,    g_S);
    cudaGetSymbolAddress((void**)&Shi,  g_Shi);
    cudaGetSymbolAddress((void**)&Slo,  g_Slo);
    cudaGetSymbolAddress((void**)&Hhi,  g_Hhi);
    cudaGetSymbolAddress((void**)&Hlo,  g_Hlo);
    cudaGetSymbolAddress((void**)&HT,   g_HT);
    cudaGetSymbolAddress((void**)&H4hi, g_H4hi);
    cudaGetSymbolAddress((void**)&H4lo, g_H4lo);
    cudaGetSymbolAddress((void**)&Wh,   g_Wh);
    cudaGetSymbolAddress((void**)&MT,   g_MT);

    const size_t HSZ = (size_t)NDIM * DDIM;
    const float* Hsrc[3] = {H, H_low, H_high};

    const int splitThreads = 256;
    const int hBlocks = (int)(HSZ / 4 / splitThreads);

    for (int j = 0; j < 3; j++) {
        split_kernel<<<hBlocks, splitThreads>>>(Hsrc[j], Hhi + j * HSZ,
                                                j == 0 ? Hlo : (__half*)nullptr, (int)HSZ);
        round_t_kernel<<<dim3(DDIM / 32, NDIM / 32), dim3(32, 8)>>>(
            Hsrc[j], NDIM, DDIM, HT + j * HSZ);
    }
    split_kernel<<<(int)((size_t)DDIM * 3 * DDIM / 4 / splitThreads), splitThreads>>>(
        W, Wh, (__half*)nullptr, (int)((size_t)DDIM * 3 * DDIM));
    mask_transpose_kernel<<<dim3(NDIM / 32, NDIM / 32), dim3(32, 8)>>>(B_low, MT);

    const float scale = 0.03125f;  // 1/sqrt(1024)
    const dim3 gScore(NDIM / BN, NDIM / BM);   // 32 x 32
    const dim3 gOut(DDIM / BN, NDIM / BM);     // 8 x 32

    const float* masks_f[3] = {L, nullptr, B_high};

    for (int j = 0; j < 3; j++) {
        // scores: S = scale * H @ H_kv^T   (A = H split, B = fp16 H_kv)
        gemm_hmma<<<gScore, 256>>>(
            Hhi, Hlo, DDIM, Hhi + j * HSZ, DDIM,
            DDIM, 0, scale, S, nullptr, nullptr, NDIM, nullptr);
        // double softmax + mask -> fp16 split probabilities
        softmax2_kernel<<<NDIM, 256>>>(S, masks_f[j], j == 1 ? MT : nullptr, Shi, Slo);
        // AV: H4[:, jD:(j+1)D] = P @ KV   (A = P split, B = fp16 KV^T, K-major)
        gemm_hmma<<<gOut, 256>>>(
            Shi, Slo, NDIM, HT + j * HSZ, NDIM,
            NDIM, 1, 1.0f, nullptr, H4hi + j * DDIM, H4lo + j * DDIM, 3 * DDIM, nullptr);
    }

    // out = tanh(H4 @ W^T + b)   (A = H4 split, B = fp16 W)
    gemm_hmma<<<gOut, 256>>>(
        H4hi, H4lo, 3 * DDIM, Wh, 3 * DDIM,
        3 * DDIM, 2, 1.0f, out, nullptr, nullptr, DDIM, bvec);
}

// round 5
// speedup vs baseline: 5.0198x; 1.3893x over previous
#include <cuda_runtime.h>
#include <cuda_fp16.h>
#include <math.h>
#include <stdint.h>

#define NDIM 4096
#define DDIM 1024

// ---------------- scratch (device globals) ----------------
__device__ float g_S[(size_t)NDIM * NDIM];                 // fp32 scores
__device__ __half g_Sh[(size_t)NDIM * NDIM];               // fp16 probabilities
__device__ __half g_Hh[3][(size_t)NDIM * DDIM];            // fp16(H / H_low / H_high)
__device__ __half g_HT[3][(size_t)DDIM * NDIM];            // fp16 transposed KV
__device__ __half g_H4hi[(size_t)NDIM * 3 * DDIM];
__device__ __half g_H4lo[(size_t)NDIM * 3 * DDIM];
__device__ __half g_Wh[(size_t)DDIM * 3 * DDIM];           // fp16(W)
__device__ unsigned char g_MT[(size_t)NDIM * NDIM];        // (B_low!=0)^T byte mask

// ---------------- PTX helpers (baseline tier) ----------------
__device__ __forceinline__ uint32_t smem_u32(const void* p) {
    uint32_t a;
    asm("{ .reg .u64 t; cvta.to.shared.u64 t, %1; cvt.u32.u64 %0, t; }" : "=r"(a) : "l"(p));
    return a;
}
__device__ __forceinline__ void cp_async16(uint32_t dst, const void* src) {
    asm volatile("cp.async.cg.shared.global [%0], [%1], 16;" :: "r"(dst), "l"(src) : "memory");
}
__device__ __forceinline__ void cp_commit() {
    asm volatile("cp.async.commit_group;" ::: "memory");
}
template <int N>
__device__ __forceinline__ void cp_wait() {
    asm volatile("cp.async.wait_group %0;" :: "n"(N) : "memory");
}
__device__ __forceinline__ void ldsm4(uint32_t* d, uint32_t addr) {
    asm volatile("ldmatrix.sync.aligned.m8n8.x4.shared.b16 {%0,%1,%2,%3}, [%4];"
        : "=r"(d[0]), "=r"(d[1]), "=r"(d[2]), "=r"(d[3]) : "r"(addr));
}
__device__ __forceinline__ void mma16816(float* c, const uint32_t* a, const uint32_t* b) {
    asm volatile("mma.sync.aligned.m16n8k16.row.col.f32.f16.f16.f32 "
        "{%0,%1,%2,%3}, {%4,%5,%6,%7}, {%8,%9}, {%0,%1,%2,%3};"
        : "+f"(c[0]), "+f"(c[1]), "+f"(c[2]), "+f"(c[3])
        : "r"(a[0]), "r"(a[1]), "r"(a[2]), "r"(a[3]), "r"(b[0]), "r"(b[1]));
}

// SMEM tile: 128 rows x 16 fp16 (32B/row), two 16B chunks/row, XOR swizzle.
__device__ __forceinline__ uint32_t soff(int r, int c) {
    return (uint32_t)(r * 32 + (((c ^ ((r >> 2) & 1))) << 4));
}

#define BM 128
#define BN 128
#define BKE 16                      // fp16 elements per k-stage
#define OPB (BM * 32)               // 4096 B per operand per stage

// ============================================================================
// HMMA NT GEMM.
//   SPLIT_A=false: C = A1 @ B^T           (single-pass fp16)
//   SPLIT_A=true : C = (A1+A2) @ B^T      (2-pass fp16 emulation)
// modes: 0: Cf = alpha*acc   1: Chi/Clo = fp16 split of acc   2: Cf = tanh(acc + bias[n])
// ============================================================================
template <bool SPLIT_A>
__global__ void __launch_bounds__(256, 2) gemm_hmma(
    const __half* __restrict__ A1, const __half* __restrict__ A2, int lda,
    const __half* __restrict__ B, int ldb,
    int K, int mode, float alpha,
    float* __restrict__ Cf, __half* __restrict__ Chi, __half* __restrict__ Clo,
    int ldc, const float* __restrict__ bias)
{
    constexpr int NOPS = SPLIT_A ? 3 : 2;
    constexpr int STB  = NOPS * OPB;            // bytes per stage
    constexpr int NST  = SPLIT_A ? 4 : 6;       // stages (48 KB both)
    __shared__ __align__(128) char sm[NST * STB];

    const int t    = threadIdx.x;
    const int lane = t & 31;
    const int wid  = t >> 5;
    const int wm   = (wid & 3) * 32;   // warp m-offset
    const int wn   = (wid >> 2) * 64;  // warp n-offset
    const int m0   = blockIdx.y * BM;
    const int n0   = blockIdx.x * BN;
    const uint32_t sbase = smem_u32(sm);

    // loader: thread t -> row lr, 16B chunk lc of each operand
    const int lr = t >> 1;
    const int lc = t & 1;
    const uint32_t st_off = soff(lr, lc);
    const __half* gA1 = A1 + (size_t)(m0 + lr) * lda + lc * 8;
    const __half* gA2 = SPLIT_A ? (A2 + (size_t)(m0 + lr) * lda + lc * 8) : nullptr;
    const __half* gB  = B  + (size_t)(n0 + lr) * ldb + lc * 8;

    // fragment smem offsets
    uint32_t adA[2], adB[4];
    {
        const int mm = lane >> 3;
#pragma unroll
        for (int i = 0; i < 2; i++)
            adA[i] = soff(wm + i * 16 + (mm & 1) * 8 + (lane & 7), mm >> 1);
#pragma unroll
        for (int j = 0; j < 4; j++)
            adB[j] = soff(wn + j * 16 + (mm >> 1) * 8 + (lane & 7), mm & 1);
    }

    float acc[2][8][4];
#pragma unroll
    for (int i = 0; i < 2; i++)
#pragma unroll
        for (int j = 0; j < 8; j++)
#pragma unroll
            for (int q = 0; q < 4; q++) acc[i][j][q] = 0.f;

    const int T = K / BKE;

    // prologue: stage tiles 0..NST-2 (one commit group per tile)
#pragma unroll
    for (int s = 0; s < NST - 1; s++) {
        const uint32_t d = sbase + s * STB + st_off;
        const int k = s * BKE;
        cp_async16(d,       gA1 + k);
        if (SPLIT_A) cp_async16(d + OPB, gA2 + k);
        cp_async16(d + (NOPS - 1) * OPB, gB + k);
        cp_commit();
    }

    for (int tt = 0; tt < T; tt++) {
        __syncthreads();   // all warps done reading the buffer being refilled
        const int nt = tt + NST - 1;
        if (nt < T) {
            const uint32_t d = sbase + (nt % NST) * STB + st_off;
            const int k = nt * BKE;
            cp_async16(d,       gA1 + k);
            if (SPLIT_A) cp_async16(d + OPB, gA2 + k);
            cp_async16(d + (NOPS - 1) * OPB, gB + k);
        }
        cp_commit();
        cp_wait<NST - 2>();   // tile tt complete
        __syncthreads();

        const uint32_t sb = sbase + (tt % NST) * STB;
        uint32_t a1[2][4], a2[2][4], b[8][2];
#pragma unroll
        for (int i = 0; i < 2; i++) {
            ldsm4(a1[i], sb + adA[i]);
            if (SPLIT_A) ldsm4(a2[i], sb + OPB + adA[i]);
        }
#pragma unroll
        for (int j = 0; j < 4; j++) {
            uint32_t tmp[4];
            ldsm4(tmp, sb + (NOPS - 1) * OPB + adB[j]);
            b[2*j][0]   = tmp[0]; b[2*j][1]   = tmp[1];
            b[2*j+1][0] = tmp[2]; b[2*j+1][1] = tmp[3];
        }
#pragma unroll
        for (int i = 0; i < 2; i++)
#pragma unroll
            for (int j = 0; j < 8; j++) {
                mma16816(acc[i][j], a1[i], b[j]);
                if (SPLIT_A) mma16816(acc[i][j], a2[i], b[j]);
            }
    }

    // epilogue
    const int row0 = m0 + wm + (lane >> 2);
    const int colb = n0 + wn + (lane & 3) * 2;
#pragma unroll
    for (int i = 0; i < 2; i++) {
#pragma unroll
        for (int j = 0; j < 8; j++) {
            const int r0 = row0 + i * 16;
            const int r1 = r0 + 8;
            const int col = colb + j * 8;
            const float* c = acc[i][j];
            if (mode == 0) {
                *(float2*)(Cf + (size_t)r0 * ldc + col) = make_float2(c[0] * alpha, c[1] * alpha);
                *(float2*)(Cf + (size_t)r1 * ldc + col) = make_float2(c[2] * alpha, c[3] * alpha);
            } else if (mode == 1) {
                __half h0 = __float2half_rn(c[0]);
                __half h1 = __float2half_rn(c[1]);
                __half h2 = __float2half_rn(c[2]);
                __half h3 = __float2half_rn(c[3]);
                __half2 hh0; hh0.x = h0; hh0.y = h1;
                __half2 hh1; hh1.x = h2; hh1.y = h3;
                __half2 ll0, ll1;
                ll0.x = __float2half_rn(c[0] - __half2float(h0));
                ll0.y = __float2half_rn(c[1] - __half2float(h1));
                ll1.x = __float2half_rn(c[2] - __half2float(h2));
                ll1.y = __float2half_rn(c[3] - __half2float(h3));
                *(__half2*)(Chi + (size_t)r0 * ldc + col) = hh0;
                *(__half2*)(Clo + (size_t)r0 * ldc + col) = ll0;
                *(__half2*)(Chi + (size_t)r1 * ldc + col) = hh1;
                *(__half2*)(Clo + (size_t)r1 * ldc + col) = ll1;
            } else {
                *(float2*)(Cf + (size_t)r0 * ldc + col) =
                    make_float2(tanhf(c[0] + bias[col]), tanhf(c[1] + bias[col + 1]));
                *(float2*)(Cf + (size_t)r1 * ldc + col) =
                    make_float2(tanhf(c[2] + bias[col]), tanhf(c[3] + bias[col + 1]));
            }
        }
    }
}

// ============================================================================
// fp32 -> fp16 round, elementwise
// ============================================================================
__global__ void round_kernel(const float* __restrict__ X,
                             __half* __restrict__ hi, int count)
{
    int i = (blockIdx.x * blockDim.x + threadIdx.x) * 4;
    if (i >= count) return;
    float4 v = *(const float4*)(X + i);
    __half2 a; a.x = __float2half_rn(v.x); a.y = __float2half_rn(v.y);
    __half2 b; b.x = __float2half_rn(v.z); b.y = __float2half_rn(v.w);
    *(__half2*)(hi + i)     = a;
    *(__half2*)(hi + i + 2) = b;
}

// ============================================================================
// fp32 [R x C] -> transposed fp16 [C x R]
// ============================================================================
__global__ void round_t_kernel(const float* __restrict__ X, int R, int C,
                               __half* __restrict__ hT)
{
    __shared__ float tile[32][33];
    const int c0 = blockIdx.x * 32;
    const int r0 = blockIdx.y * 32;
    const int tx = threadIdx.x;
    const int ty = threadIdx.y;
#pragma unroll
    for (int j = ty; j < 32; j += 8)
        tile[j][tx] = X[(size_t)(r0 + j) * C + c0 + tx];
    __syncthreads();
#pragma unroll
    for (int j = ty; j < 32; j += 8)
        hT[(size_t)(c0 + j) * R + r0 + tx] = __float2half_rn(tile[tx][j]);
}

// ============================================================================
// double softmax with mask; reads fp32 S, writes fp16 probabilities
// ============================================================================
__device__ __forceinline__ float warp_red_max(float v) {
#pragma unroll
    for (int o = 16; o; o >>= 1) v = fmaxf(v, __shfl_xor_sync(0xffffffffu, v, o));
    return v;
}
__device__ __forceinline__ float warp_red_sum(float v) {
#pragma unroll
    for (int o = 16; o; o >>= 1) v += __shfl_xor_sync(0xffffffffu, v, o);
    return v;
}
template <bool IS_MAX>
__device__ __forceinline__ float block_red(float v, float* red, int t) {
    v = IS_MAX ? warp_red_max(v) : warp_red_sum(v);
    __syncthreads();
    if ((t & 31) == 0) red[t >> 5] = v;
    __syncthreads();
    if (t < 32) {
        float x = (t < 8) ? red[t] : (IS_MAX ? -INFINITY : 0.f);
        x = IS_MAX ? warp_red_max(x) : warp_red_sum(x);
        if (t == 0) red[0] = x;
    }
    __syncthreads();
    return red[0];
}

__global__ void __launch_bounds__(256) softmax2_kernel(
    const float* __restrict__ S,
    const float* __restrict__ maskf,
    const unsigned char* __restrict__ maskb,
    __half* __restrict__ P)
{
    __shared__ __align__(16) float buf[NDIM];
    __shared__ float red[32];
    const int t = threadIdx.x;
    const int row = blockIdx.x;
    const float* Srow = S + (size_t)row * NDIM;

    float mx = -INFINITY;
#pragma unroll
    for (int i = t * 4; i < NDIM; i += 1024) {
        float4 v = *(const float4*)(Srow + i);
        *(float4*)&buf[i] = v;
        mx = fmaxf(mx, fmaxf(fmaxf(v.x, v.y), fmaxf(v.z, v.w)));
    }
    const float smax = block_red<true>(mx, red, t);

    float sum = 0.f;
#pragma unroll
    for (int i = t * 4; i < NDIM; i += 1024) {
        float4 v = *(float4*)&buf[i];
        v.x = __expf(v.x - smax); v.y = __expf(v.y - smax);
        v.z = __expf(v.z - smax); v.w = __expf(v.w - smax);
        *(float4*)&buf[i] = v;
        sum += v.x + v.y + v.z + v.w;
    }
    const float inv = 1.f / block_red<false>(sum, red, t);

    float mx2 = -INFINITY;
#pragma unroll
    for (int i = t * 4; i < NDIM; i += 1024) {
        float4 v = *(float4*)&buf[i];
        float4 m;
        if (maskf) {
            float4 mm = *(const float4*)(maskf + (size_t)row * NDIM + i);
            m.x = (mm.x != 0.f) ? 1.f : 0.f;
            m.y = (mm.y != 0.f) ? 1.f : 0.f;
            m.z = (mm.z != 0.f) ? 1.f : 0.f;
            m.w = (mm.w != 0.f) ? 1.f : 0.f;
        } else {
            uchar4 mm = *(const uchar4*)(maskb + (size_t)row * NDIM + i);
            m.x = (float)mm.x; m.y = (float)mm.y; m.z = (float)mm.z; m.w = (float)mm.w;
        }
        v.x = v.x * inv * m.x; v.y = v.y * inv * m.y;
        v.z = v.z * inv * m.z; v.w = v.w * inv * m.w;
        *(float4*)&buf[i] = v;
        mx2 = fmaxf(mx2, fmaxf(fmaxf(v.x, v.y), fmaxf(v.z, v.w)));
    }
    const float smax2 = block_red<true>(mx2, red, t);

    float sum2 = 0.f;
#pragma unroll
    for (int i = t * 4; i < NDIM; i += 1024) {
        float4 v = *(float4*)&buf[i];
        v.x = __expf(v.x - smax2); v.y = __expf(v.y - smax2);
        v.z = __expf(v.z - smax2); v.w = __expf(v.w - smax2);
        *(float4*)&buf[i] = v;
        sum2 += v.x + v.y + v.z + v.w;
    }
    const float inv2 = 1.f / block_red<false>(sum2, red, t);

    __half* prow = P + (size_t)row * NDIM;
#pragma unroll
    for (int i = t * 4; i < NDIM; i += 1024) {
        float4 v = *(float4*)&buf[i];
        __half2 a; a.x = __float2half_rn(v.x * inv2); a.y = __float2half_rn(v.y * inv2);
        __half2 b; b.x = __float2half_rn(v.z * inv2); b.y = __float2half_rn(v.w * inv2);
        *(__half2*)(prow + i)     = a;
        *(__half2*)(prow + i + 2) = b;
    }
}

// ============================================================================
// transposed byte mask: MT[r][c] = (B[c][r] != 0)
// ============================================================================
__global__ void mask_transpose_kernel(const float* __restrict__ B,
                                      unsigned char* __restrict__ MT)
{
    __shared__ unsigned char tile[32][33];
    const int bx = blockIdx.x * 32;
    const int by = blockIdx.y * 32;
    const int tx = threadIdx.x;
    const int ty = threadIdx.y;
#pragma unroll
    for (int j = ty; j < 32; j += 8)
        tile[j][tx] = (B[(size_t)(by + j) * NDIM + bx + tx] != 0.f) ? 1 : 0;
    __syncthreads();
#pragma unroll
    for (int j = ty; j < 32; j += 8)
        MT[(size_t)(bx + j) * NDIM + by + tx] = tile[tx][j];
}

// ============================================================================
// launch
// ============================================================================
extern "C" void kernel_launch(void* const* d_in, const int* in_sizes, int n_in,
                              void* d_out, int out_size)
{
    const float* L      = (const float*)d_in[0];
    const float* H      = (const float*)d_in[1];
    const float* B_low  = (const float*)d_in[2];
    const float* H_low  = (const float*)d_in[3];
    const float* B_high = (const float*)d_in[4];
    const float* H_high = (const float*)d_in[5];
    const float* W      = (const float*)d_in[6];
    const float* bvec   = (const float*)d_in[7];
    float* out = (float*)d_out;

    float* S;
    __half *Sh, *Hh, *HT, *H4hi, *H4lo, *Wh;
    unsigned char* MT;
    cudaGetSymbolAddress((void**)&S,    g_S);
    cudaGetSymbolAddress((void**)&Sh,   g_Sh);
    cudaGetSymbolAddress((void**)&Hh,   g_Hh);
    cudaGetSymbolAddress((void**)&HT,   g_HT);
    cudaGetSymbolAddress((void**)&H4hi, g_H4hi);
    cudaGetSymbolAddress((void**)&H4lo, g_H4lo);
    cudaGetSymbolAddress((void**)&Wh,   g_Wh);
    cudaGetSymbolAddress((void**)&MT,   g_MT);

    const size_t HSZ = (size_t)NDIM * DDIM;
    const float* Hsrc[3] = {H, H_low, H_high};

    const int splitThreads = 256;
    const int hBlocks = (int)(HSZ / 4 / splitThreads);

    for (int j = 0; j < 3; j++) {
        round_kernel<<<hBlocks, splitThreads>>>(Hsrc[j], Hh + j * HSZ, (int)HSZ);
        round_t_kernel<<<dim3(DDIM / 32, NDIM / 32), dim3(32, 8)>>>(
            Hsrc[j], NDIM, DDIM, HT + j * HSZ);
    }
    round_kernel<<<(int)((size_t)DDIM * 3 * DDIM / 4 / splitThreads), splitThreads>>>(
        W, Wh, (int)((size_t)DDIM * 3 * DDIM));
    mask_transpose_kernel<<<dim3(NDIM / 32, NDIM / 32), dim3(32, 8)>>>(B_low, MT);

    const float scale = 0.03125f;  // 1/sqrt(1024)
    const dim3 gScore(NDIM / BN, NDIM / BM);   // 32 x 32
    const dim3 gOut(DDIM / BN, NDIM / BM);     // 8 x 32

    const float* masks_f[3] = {L, nullptr, B_high};

    for (int j = 0; j < 3; j++) {
        // scores: S = scale * H @ H_kv^T   (single-pass fp16)
        gemm_hmma<false><<<gScore, 256>>>(
            Hh, nullptr, DDIM, Hh + j * HSZ, DDIM,
            DDIM, 0, scale, S, nullptr, nullptr, NDIM, nullptr);
        // double softmax + mask -> fp16 probabilities
        softmax2_kernel<<<NDIM, 256>>>(S, masks_f[j], j == 1 ? MT : nullptr, Sh);
        // AV: H4[:, jD:(j+1)D] = P @ KV   (single-pass fp16, epilogue emits hi/lo)
        gemm_hmma<false><<<gOut, 256>>>(
            Sh, nullptr, NDIM, HT + j * HSZ, NDIM,
            NDIM, 1, 1.0f, nullptr, H4hi + j * DDIM, H4lo + j * DDIM, 3 * DDIM, nullptr);
    }

    // out = tanh(H4 @ W^T + b)   (2-pass fp16 emulation on A)
    gemm_hmma<true><<<gOut, 256>>>(
        H4hi, H4lo, 3 * DDIM, Wh, 3 * DDIM,
        3 * DDIM, 2, 1.0f, out, nullptr, nullptr, DDIM, bvec);
}

// round 6
// speedup vs baseline: 6.2763x; 1.2503x over previous
#include <cuda_runtime.h>
#include <cuda_fp16.h>
#include <math.h>
#include <stdint.h>

#define NDIM 4096
#define DDIM 1024

// ---------------- scratch (device globals) ----------------
__device__ __half g_Sh[3][(size_t)NDIM * NDIM];            // fp16 scores -> probs (in place)
__device__ __half g_Hh[3][(size_t)NDIM * DDIM];            // fp16(H / H_low / H_high)
__device__ __half g_HT[3][(size_t)DDIM * NDIM];            // fp16 transposed KV
__device__ __half g_H4[(size_t)NDIM * 3 * DDIM];           // fp16 concat AV outputs
__device__ __half g_Wh[(size_t)DDIM * 3 * DDIM];           // fp16(W)
__device__ unsigned char g_MT[(size_t)NDIM * NDIM];        // (B_low!=0)^T byte mask

// ---------------- PTX helpers (baseline tier) ----------------
__device__ __forceinline__ uint32_t smem_u32(const void* p) {
    uint32_t a;
    asm("{ .reg .u64 t; cvta.to.shared.u64 t, %1; cvt.u32.u64 %0, t; }" : "=r"(a) : "l"(p));
    return a;
}
__device__ __forceinline__ void cp_async16(uint32_t dst, const void* src) {
    asm volatile("cp.async.cg.shared.global [%0], [%1], 16;" :: "r"(dst), "l"(src) : "memory");
}
__device__ __forceinline__ void cp_commit() {
    asm volatile("cp.async.commit_group;" ::: "memory");
}
template <int N>
__device__ __forceinline__ void cp_wait() {
    asm volatile("cp.async.wait_group %0;" :: "n"(N) : "memory");
}
__device__ __forceinline__ void ldsm4(uint32_t* d, uint32_t addr) {
    asm volatile("ldmatrix.sync.aligned.m8n8.x4.shared.b16 {%0,%1,%2,%3}, [%4];"
        : "=r"(d[0]), "=r"(d[1]), "=r"(d[2]), "=r"(d[3]) : "r"(addr));
}
__device__ __forceinline__ void mma16816(float* c, const uint32_t* a, const uint32_t* b) {
    asm volatile("mma.sync.aligned.m16n8k16.row.col.f32.f16.f16.f32 "
        "{%0,%1,%2,%3}, {%4,%5,%6,%7}, {%8,%9}, {%0,%1,%2,%3};"
        : "+f"(c[0]), "+f"(c[1]), "+f"(c[2]), "+f"(c[3])
        : "r"(a[0]), "r"(a[1]), "r"(a[2]), "r"(a[3]), "r"(b[0]), "r"(b[1]));
}

// SMEM tile: 128 rows x 32 fp16 (64B/row), four 16B chunks/row, XOR swizzle.
// Conflict-free for both cp.async 16B stores and ldmatrix reads.
__device__ __forceinline__ uint32_t soff64(int r, int c) {
    return (uint32_t)(r * 64 + ((c ^ ((r >> 1) & 3)) << 4));
}

#define OPB (128 * 64)      // 8192 B per operand tile per stage
#define STB (2 * OPB)       // 16 KB per stage (A, B)
#define NST 3               // 48 KB static smem, exact
#define BKE 32              // fp16 k-elements per stage

// ============================================================================
// HMMA NT GEMM, single-pass fp16:  C[M,N] = A[M,K] @ B[N,K]^T, per-z operands.
// mode 0: Ch = fp16(alpha * acc)      mode 1: Cf = tanh(acc + bias[n])
// ============================================================================
__global__ void __launch_bounds__(256, 2) gemm_hmma(
    const __half* __restrict__ A, size_t sAz, int lda,
    const __half* __restrict__ B, size_t sBz, int ldb,
    int K, int mode, float alpha,
    __half* __restrict__ Ch, float* __restrict__ Cf, size_t sCz, int ldc,
    const float* __restrict__ bias)
{
    __shared__ __align__(128) char sm[NST * STB];

    const int t    = threadIdx.x;
    const int lane = t & 31;
    const int wid  = t >> 5;
    const int wm   = (wid & 3) * 32;
    const int wn   = (wid >> 2) * 64;
    const int m0   = blockIdx.y * 128;
    const int n0   = blockIdx.x * 128;
    const int z    = blockIdx.z;
    A += (size_t)z * sAz;
    B += (size_t)z * sBz;
    const uint32_t sbase = smem_u32(sm);

    // loader: thread t covers chunks t and t+256 of each 512-chunk operand tile
    const int rl = t >> 2;            // rows 0..63 (and +64 for second chunk)
    const int cl = t & 3;
    const uint32_t st0 = soff64(rl, cl);
    const uint32_t st1 = soff64(rl + 64, cl);
    const __half* gA0 = A + (size_t)(m0 + rl) * lda + cl * 8;
    const __half* gA1 = A + (size_t)(m0 + rl + 64) * lda + cl * 8;
    const __half* gB0 = B + (size_t)(n0 + rl) * ldb + cl * 8;
    const __half* gB1 = B + (size_t)(n0 + rl + 64) * ldb + cl * 8;

    // fragment smem offsets, both k-steps
    uint32_t adA[2][2], adB[2][4];
    {
        const int mm = lane >> 3;
#pragma unroll
        for (int ks = 0; ks < 2; ks++) {
#pragma unroll
            for (int i = 0; i < 2; i++)
                adA[ks][i] = soff64(wm + i * 16 + (mm & 1) * 8 + (lane & 7),
                                    2 * ks + (mm >> 1));
#pragma unroll
            for (int j = 0; j < 4; j++)
                adB[ks][j] = soff64(wn + j * 16 + (mm >> 1) * 8 + (lane & 7),
                                    2 * ks + (mm & 1));
        }
    }

    float acc[2][8][4];
#pragma unroll
    for (int i = 0; i < 2; i++)
#pragma unroll
        for (int j = 0; j < 8; j++)
#pragma unroll
            for (int q = 0; q < 4; q++) acc[i][j][q] = 0.f;

    const int T = K / BKE;

    // prologue
#pragma unroll
    for (int s = 0; s < NST - 1; s++) {
        const uint32_t d = sbase + s * STB;
        const int k = s * BKE;
        cp_async16(d + st0,       gA0 + k);
        cp_async16(d + st1,       gA1 + k);
        cp_async16(d + OPB + st0, gB0 + k);
        cp_async16(d + OPB + st1, gB1 + k);
        cp_commit();
    }

    for (int tt = 0; tt < T; tt++) {
        __syncthreads();   // all warps done with the buffer being refilled
        const int nt = tt + NST - 1;
        if (nt < T) {
            const uint32_t d = sbase + (nt % NST) * STB;
            const int k = nt * BKE;
            cp_async16(d + st0,       gA0 + k);
            cp_async16(d + st1,       gA1 + k);
            cp_async16(d + OPB + st0, gB0 + k);
            cp_async16(d + OPB + st1, gB1 + k);
        }
        cp_commit();
        cp_wait<NST - 2>();
        __syncthreads();

        const uint32_t sb = sbase + (tt % NST) * STB;
#pragma unroll
        for (int ks = 0; ks < 2; ks++) {
            uint32_t a[2][4], b[8][2];
            ldsm4(a[0], sb + adA[ks][0]);
            ldsm4(a[1], sb + adA[ks][1]);
#pragma unroll
            for (int j = 0; j < 4; j++) {
                uint32_t tmp[4];
                ldsm4(tmp, sb + OPB + adB[ks][j]);
                b[2*j][0]   = tmp[0]; b[2*j][1]   = tmp[1];
                b[2*j+1][0] = tmp[2]; b[2*j+1][1] = tmp[3];
            }
#pragma unroll
            for (int i = 0; i < 2; i++)
#pragma unroll
                for (int j = 0; j < 8; j++)
                    mma16816(acc[i][j], a[i], b[j]);
        }
    }

    // epilogue
    const int row0 = m0 + wm + (lane >> 2);
    const int colb = n0 + wn + (lane & 3) * 2;
    if (mode == 0) {
        __half* Cz = Ch + (size_t)z * sCz;
#pragma unroll
        for (int i = 0; i < 2; i++) {
#pragma unroll
            for (int j = 0; j < 8; j++) {
                const int r0 = row0 + i * 16;
                const int col = colb + j * 8;
                const float* c = acc[i][j];
                __half2 v0; v0.x = __float2half_rn(c[0] * alpha); v0.y = __float2half_rn(c[1] * alpha);
                __half2 v1; v1.x = __float2half_rn(c[2] * alpha); v1.y = __float2half_rn(c[3] * alpha);
                *(__half2*)(Cz + (size_t)r0 * ldc + col)       = v0;
                *(__half2*)(Cz + (size_t)(r0 + 8) * ldc + col) = v1;
            }
        }
    } else {
#pragma unroll
        for (int i = 0; i < 2; i++) {
#pragma unroll
            for (int j = 0; j < 8; j++) {
                const int r0 = row0 + i * 16;
                const int col = colb + j * 8;
                const float* c = acc[i][j];
                *(float2*)(Cf + (size_t)r0 * ldc + col) =
                    make_float2(tanhf(c[0] + bias[col]), tanhf(c[1] + bias[col + 1]));
                *(float2*)(Cf + (size_t)(r0 + 8) * ldc + col) =
                    make_float2(tanhf(c[2] + bias[col]), tanhf(c[3] + bias[col + 1]));
            }
        }
    }
}

// ============================================================================
// fp32 -> fp16 round, elementwise
// ============================================================================
__global__ void round_kernel(const float* __restrict__ X,
                             __half* __restrict__ hi, int count)
{
    int i = (blockIdx.x * blockDim.x + threadIdx.x) * 4;
    if (i >= count) return;
    float4 v = *(const float4*)(X + i);
    __half2 a; a.x = __float2half_rn(v.x); a.y = __float2half_rn(v.y);
    __half2 b; b.x = __float2half_rn(v.z); b.y = __float2half_rn(v.w);
    *(__half2*)(hi + i)     = a;
    *(__half2*)(hi + i + 2) = b;
}

// ============================================================================
// fp32 [R x C] -> transposed fp16 [C x R]
// ============================================================================
__global__ void round_t_kernel(const float* __restrict__ X, int R, int C,
                               __half* __restrict__ hT)
{
    __shared__ float tile[32][33];
    const int c0 = blockIdx.x * 32;
    const int r0 = blockIdx.y * 32;
    const int tx = threadIdx.x;
    const int ty = threadIdx.y;
#pragma unroll
    for (int j = ty; j < 32; j += 8)
        tile[j][tx] = X[(size_t)(r0 + j) * C + c0 + tx];
    __syncthreads();
#pragma unroll
    for (int j = ty; j < 32; j += 8)
        hT[(size_t)(c0 + j) * R + r0 + tx] = __float2half_rn(tile[tx][j]);
}

// ============================================================================
// merged double softmax with mask; fp16 in/out (in place), grid (NDIM, 3)
// ============================================================================
__device__ __forceinline__ float warp_red_max(float v) {
#pragma unroll
    for (int o = 16; o; o >>= 1) v = fmaxf(v, __shfl_xor_sync(0xffffffffu, v, o));
    return v;
}
__device__ __forceinline__ float warp_red_sum(float v) {
#pragma unroll
    for (int o = 16; o; o >>= 1) v += __shfl_xor_sync(0xffffffffu, v, o);
    return v;
}
template <bool IS_MAX>
__device__ __forceinline__ float block_red(float v, float* red, int t) {
    v = IS_MAX ? warp_red_max(v) : warp_red_sum(v);
    __syncthreads();
    if ((t & 31) == 0) red[t >> 5] = v;
    __syncthreads();
    if (t < 32) {
        float x = (t < 8) ? red[t] : (IS_MAX ? -INFINITY : 0.f);
        x = IS_MAX ? warp_red_max(x) : warp_red_sum(x);
        if (t == 0) red[0] = x;
    }
    __syncthreads();
    return red[0];
}

__global__ void __launch_bounds__(256) softmax2_kernel(
    __half* __restrict__ Sbase,
    const float* __restrict__ Lm,
    const unsigned char* __restrict__ MT,
    const float* __restrict__ Bhigh)
{
    __shared__ __align__(16) float buf[NDIM];
    __shared__ float red[32];
    const int t = threadIdx.x;
    const int row = blockIdx.x;
    const int br = blockIdx.y;
    __half* Srow = Sbase + (size_t)br * NDIM * NDIM + (size_t)row * NDIM;
    const float* maskf = (br == 0) ? (Lm + (size_t)row * NDIM)
                       : (br == 2) ? (Bhigh + (size_t)row * NDIM) : nullptr;
    const unsigned char* maskb = (br == 1) ? (MT + (size_t)row * NDIM) : nullptr;

    // pass 1: load fp16 -> fp32 buf, max
    float mx = -INFINITY;
#pragma unroll
    for (int i = t * 8; i < NDIM; i += 2048) {
        uint4 raw = *(const uint4*)(Srow + i);
        const __half2* h2 = (const __half2*)&raw;
#pragma unroll
        for (int q = 0; q < 4; q++) {
            float2 f = __half22float2(h2[q]);
            buf[i + 2*q]     = f.x;
            buf[i + 2*q + 1] = f.y;
            mx = fmaxf(mx, fmaxf(f.x, f.y));
        }
    }
    const float smax = block_red<true>(mx, red, t);

    // pass 2: exp + sum
    float sum = 0.f;
#pragma unroll
    for (int i = t * 4; i < NDIM; i += 1024) {
        float4 v = *(float4*)&buf[i];
        v.x = __expf(v.x - smax); v.y = __expf(v.y - smax);
        v.z = __expf(v.z - smax); v.w = __expf(v.w - smax);
        *(float4*)&buf[i] = v;
        sum += v.x + v.y + v.z + v.w;
    }
    const float inv = 1.f / block_red<false>(sum, red, t);

    // pass 3: normalize + mask + max2
    float mx2 = -INFINITY;
#pragma unroll
    for (int i = t * 4; i < NDIM; i += 1024) {
        float4 v = *(float4*)&buf[i];
        float4 m;
        if (maskf) {
            float4 mm = *(const float4*)(maskf + i);
            m.x = (mm.x != 0.f) ? 1.f : 0.f;
            m.y = (mm.y != 0.f) ? 1.f : 0.f;
            m.z = (mm.z != 0.f) ? 1.f : 0.f;
            m.w = (mm.w != 0.f) ? 1.f : 0.f;
        } else {
            uchar4 mm = *(const uchar4*)(maskb + i);
            m.x = (float)mm.x; m.y = (float)mm.y; m.z = (float)mm.z; m.w = (float)mm.w;
        }
        v.x = v.x * inv * m.x; v.y = v.y * inv * m.y;
        v.z = v.z * inv * m.z; v.w = v.w * inv * m.w;
        *(float4*)&buf[i] = v;
        mx2 = fmaxf(mx2, fmaxf(fmaxf(v.x, v.y), fmaxf(v.z, v.w)));
    }
    const float smax2 = block_red<true>(mx2, red, t);

    // pass 4: exp + sum
    float sum2 = 0.f;
#pragma unroll
    for (int i = t * 4; i < NDIM; i += 1024) {
        float4 v = *(float4*)&buf[i];
        v.x = __expf(v.x - smax2); v.y = __expf(v.y - smax2);
        v.z = __expf(v.z - smax2); v.w = __expf(v.w - smax2);
        *(float4*)&buf[i] = v;
        sum2 += v.x + v.y + v.z + v.w;
    }
    const float inv2 = 1.f / block_red<false>(sum2, red, t);

    // pass 5: write fp16 back in place
#pragma unroll
    for (int i = t * 8; i < NDIM; i += 2048) {
        uint4 raw;
        __half2* h2 = (__half2*)&raw;
#pragma unroll
        for (int q = 0; q < 4; q++) {
            h2[q].x = __float2half_rn(buf[i + 2*q] * inv2);
            h2[q].y = __float2half_rn(buf[i + 2*q + 1] * inv2);
        }
        *(uint4*)(Srow + i) = raw;
    }
}

// ============================================================================
// transposed byte mask: MT[r][c] = (B[c][r] != 0)
// ============================================================================
__global__ void mask_transpose_kernel(const float* __restrict__ B,
                                      unsigned char* __restrict__ MT)
{
    __shared__ unsigned char tile[32][33];
    const int bx = blockIdx.x * 32;
    const int by = blockIdx.y * 32;
    const int tx = threadIdx.x;
    const int ty = threadIdx.y;
#pragma unroll
    for (int j = ty; j < 32; j += 8)
        tile[j][tx] = (B[(size_t)(by + j) * NDIM + bx + tx] != 0.f) ? 1 : 0;
    __syncthreads();
#pragma unroll
    for (int j = ty; j < 32; j += 8)
        MT[(size_t)(bx + j) * NDIM + by + tx] = tile[tx][j];
}

// ============================================================================
// launch
// ============================================================================
extern "C" void kernel_launch(void* const* d_in, const int* in_sizes, int n_in,
                              void* d_out, int out_size)
{
    const float* L      = (const float*)d_in[0];
    const float* H      = (const float*)d_in[1];
    const float* B_low  = (const float*)d_in[2];
    const float* H_low  = (const float*)d_in[3];
    const float* B_high = (const float*)d_in[4];
    const float* H_high = (const float*)d_in[5];
    const float* W      = (const float*)d_in[6];
    const float* bvec   = (const float*)d_in[7];
    float* out = (float*)d_out;

    __half *Sh, *Hh, *HT, *H4, *Wh;
    unsigned char* MT;
    cudaGetSymbolAddress((void**)&Sh, g_Sh);
    cudaGetSymbolAddress((void**)&Hh, g_Hh);
    cudaGetSymbolAddress((void**)&HT, g_HT);
    cudaGetSymbolAddress((void**)&H4, g_H4);
    cudaGetSymbolAddress((void**)&Wh, g_Wh);
    cudaGetSymbolAddress((void**)&MT, g_MT);

    const size_t HSZ = (size_t)NDIM * DDIM;
    const size_t NN  = (size_t)NDIM * NDIM;
    const float scale = 0.03125f;  // 1/sqrt(1024)
    const int rt = 256;

    // [0..2] fp16 rounds of H, H_low, H_high
    round_kernel<<<(int)(HSZ / 4 / rt), rt>>>(H,      Hh + 0 * HSZ, (int)HSZ);
    round_kernel<<<(int)(HSZ / 4 / rt), rt>>>(H_low,  Hh + 1 * HSZ, (int)HSZ);
    round_kernel<<<(int)(HSZ / 4 / rt), rt>>>(H_high, Hh + 2 * HSZ, (int)HSZ);
    // [3] W round, [4] transposed mask
    round_kernel<<<(int)((size_t)DDIM * 3 * DDIM / 4 / rt), rt>>>(
        W, Wh, (int)((size_t)DDIM * 3 * DDIM));
    mask_transpose_kernel<<<dim3(NDIM / 32, NDIM / 32), dim3(32, 8)>>>(B_low, MT);

    // [5] merged score GEMM (profiled by ncu -s 5): S_z = scale * H @ Hh_z^T
    gemm_hmma<<<dim3(NDIM / 128, NDIM / 128, 3), 256>>>(
        Hh, 0, DDIM, Hh, HSZ, DDIM,
        DDIM, 0, scale, Sh, nullptr, NN, NDIM, nullptr);

    // [6..8] transposed KV copies
    round_t_kernel<<<dim3(DDIM / 32, NDIM / 32), dim3(32, 8)>>>(H,      NDIM, DDIM, HT + 0 * HSZ);
    round_t_kernel<<<dim3(DDIM / 32, NDIM / 32), dim3(32, 8)>>>(H_low,  NDIM, DDIM, HT + 1 * HSZ);
    round_t_kernel<<<dim3(DDIM / 32, NDIM / 32), dim3(32, 8)>>>(H_high, NDIM, DDIM, HT + 2 * HSZ);

    // [9] merged double softmax (in place, fp16)
    softmax2_kernel<<<dim3(NDIM, 3), 256>>>(Sh, L, MT, B_high);

    // [10] merged AV GEMM: H4[:, zD:(z+1)D] = P_z @ KV_z
    gemm_hmma<<<dim3(DDIM / 128, NDIM / 128, 3), 256>>>(
        Sh, NN, NDIM, HT, HSZ, NDIM,
        NDIM, 0, 1.0f, H4, nullptr, DDIM, 3 * DDIM, nullptr);

    // [11] out = tanh(H4 @ W^T + b)
    gemm_hmma<<<dim3(DDIM / 128, NDIM / 128, 1), 256>>>(
        H4, 0, 3 * DDIM, Wh, 0, 3 * DDIM,
        3 * DDIM, 1, 1.0f, nullptr, out, 0, DDIM, bvec);
}

// round 7
// speedup vs baseline: 6.3057x; 1.0047x over previous
#include <cuda_runtime.h>
#include <cuda_fp16.h>
#include <cuda_fp8.h>
#include <math.h>
#include <stdint.h>

#define NDIM 4096
#define DDIM 1024

// ---------------- scratch (device globals) ----------------
__device__ __half g_Sh[3][(size_t)NDIM * NDIM];            // fp16 scores -> probs (in place)
__device__ unsigned char g_H8[3][(size_t)NDIM * DDIM];     // e4m3(H / H_low / H_high), K-major
__device__ __half g_HT[3][(size_t)DDIM * NDIM];            // fp16 transposed KV
__device__ __half g_H4[(size_t)NDIM * 3 * DDIM];           // fp16 concat AV outputs
__device__ __half g_Wh[(size_t)DDIM * 3 * DDIM];           // fp16(W)
__device__ unsigned char g_MT[(size_t)NDIM * NDIM];        // (B_low!=0)^T byte mask

// ---------------- PTX helpers (portable tier) ----------------
__device__ __forceinline__ uint32_t smem_u32(const void* p) {
    uint32_t a;
    asm("{ .reg .u64 t; cvta.to.shared.u64 t, %1; cvt.u32.u64 %0, t; }" : "=r"(a) : "l"(p));
    return a;
}
__device__ __forceinline__ void cp_async16(uint32_t dst, const void* src) {
    asm volatile("cp.async.cg.shared.global [%0], [%1], 16;" :: "r"(dst), "l"(src) : "memory");
}
__device__ __forceinline__ void cp_commit() {
    asm volatile("cp.async.commit_group;" ::: "memory");
}
template <int N>
__device__ __forceinline__ void cp_wait() {
    asm volatile("cp.async.wait_group %0;" :: "n"(N) : "memory");
}
__device__ __forceinline__ void ldsm4(uint32_t* d, uint32_t addr) {
    asm volatile("ldmatrix.sync.aligned.m8n8.x4.shared.b16 {%0,%1,%2,%3}, [%4];"
        : "=r"(d[0]), "=r"(d[1]), "=r"(d[2]), "=r"(d[3]) : "r"(addr));
}
__device__ __forceinline__ void mma_f16(float* c, const uint32_t* a, const uint32_t* b) {
    asm volatile("mma.sync.aligned.m16n8k16.row.col.f32.f16.f16.f32 "
        "{%0,%1,%2,%3}, {%4,%5,%6,%7}, {%8,%9}, {%0,%1,%2,%3};"
        : "+f"(c[0]), "+f"(c[1]), "+f"(c[2]), "+f"(c[3])
        : "r"(a[0]), "r"(a[1]), "r"(a[2]), "r"(a[3]), "r"(b[0]), "r"(b[1]));
}
__device__ __forceinline__ void mma_e4m3(float* c, const uint32_t* a, const uint32_t* b) {
    asm volatile("mma.sync.aligned.m16n8k32.row.col.f32.e4m3.e4m3.f32 "
        "{%0,%1,%2,%3}, {%4,%5,%6,%7}, {%8,%9}, {%0,%1,%2,%3};"
        : "+f"(c[0]), "+f"(c[1]), "+f"(c[2]), "+f"(c[3])
        : "r"(a[0]), "r"(a[1]), "r"(a[2]), "r"(a[3]), "r"(b[0]), "r"(b[1]));
}

// SMEM tile: 128 rows x 64 BYTES (4 x 16B chunks), XOR swizzle.
// Holds 32 fp16 or 64 fp8 k-elements per row; byte layout identical.
__device__ __forceinline__ uint32_t soff64(int r, int c) {
    return (uint32_t)(r * 64 + ((c ^ ((r >> 1) & 3)) << 4));
}

#define OPB (128 * 64)      // 8192 B per operand tile per stage
#define STB (2 * OPB)       // 16 KB per stage (A, B)
#define NST 3               // 48 KB static smem, exact

// ============================================================================
// Tensor-core NT GEMM, byte-layout-shared fp16 / fp8 paths.
//   FP8=false: C = A @ B^T over fp16  (BKE=32 elems/stage, mma k16)
//   FP8=true : C = A @ B^T over e4m3 (BKE=64 elems/stage, mma k32)
// Strides lda/ldb/sAz/sBz in ELEMENTS. K in elements.
// mode 0: Ch = fp16(alpha * acc)      mode 1: Cf = tanh(acc + bias[n])
// ============================================================================
template <bool FP8>
__global__ void __launch_bounds__(256, 2) gemm_tcore(
    const void* __restrict__ Av, size_t sAz, int lda,
    const void* __restrict__ Bv, size_t sBz, int ldb,
    int K, int mode, float alpha,
    __half* __restrict__ Ch, float* __restrict__ Cf, size_t sCz, int ldc,
    const float* __restrict__ bias)
{
    constexpr int ES = FP8 ? 1 : 2;   // bytes per element
    __shared__ __align__(128) char sm[NST * STB];

    const int t    = threadIdx.x;
    const int lane = t & 31;
    const int wid  = t >> 5;
    const int wm   = (wid & 3) * 32;
    const int wn   = (wid >> 2) * 64;
    const int m0   = blockIdx.y * 128;
    const int n0   = blockIdx.x * 128;
    const int z    = blockIdx.z;
    const uint32_t sbase = smem_u32(sm);

    // loader: thread t covers 16B chunk (rl, cl) and (rl+64, cl) of each operand
    const int rl = t >> 2;
    const int cl = t & 3;
    const uint32_t st0 = soff64(rl, cl);
    const uint32_t st1 = soff64(rl + 64, cl);
    const char* gA0 = (const char*)Av + ((size_t)z * sAz + (size_t)(m0 + rl) * lda) * ES + cl * 16;
    const char* gA1 = (const char*)Av + ((size_t)z * sAz + (size_t)(m0 + rl + 64) * lda) * ES + cl * 16;
    const char* gB0 = (const char*)Bv + ((size_t)z * sBz + (size_t)(n0 + rl) * ldb) * ES + cl * 16;
    const char* gB1 = (const char*)Bv + ((size_t)z * sBz + (size_t)(n0 + rl + 64) * ldb) * ES + cl * 16;

    // fragment smem offsets, both k-steps of a stage (k-step = 32B along k)
    uint32_t adA[2][2], adB[2][4];
    {
        const int mm = lane >> 3;
#pragma unroll
        for (int ks = 0; ks < 2; ks++) {
#pragma unroll
            for (int i = 0; i < 2; i++)
                adA[ks][i] = soff64(wm + i * 16 + (mm & 1) * 8 + (lane & 7),
                                    2 * ks + (mm >> 1));
#pragma unroll
            for (int j = 0; j < 4; j++)
                adB[ks][j] = soff64(wn + j * 16 + (mm >> 1) * 8 + (lane & 7),
                                    2 * ks + (mm & 1));
        }
    }

    float acc[2][8][4];
#pragma unroll
    for (int i = 0; i < 2; i++)
#pragma unroll
        for (int j = 0; j < 8; j++)
#pragma unroll
            for (int q = 0; q < 4; q++) acc[i][j][q] = 0.f;

    const int T = (K * ES) / 64;      // stages of 64 bytes along k

    // prologue
#pragma unroll
    for (int s = 0; s < NST - 1; s++) {
        const uint32_t d = sbase + s * STB;
        const size_t kb = (size_t)s * 64;
        cp_async16(d + st0,       gA0 + kb);
        cp_async16(d + st1,       gA1 + kb);
        cp_async16(d + OPB + st0, gB0 + kb);
        cp_async16(d + OPB + st1, gB1 + kb);
        cp_commit();
    }

    for (int tt = 0; tt < T; tt++) {
        __syncthreads();   // all warps done with the buffer being refilled
        const int nt = tt + NST - 1;
        if (nt < T) {
            const uint32_t d = sbase + (nt % NST) * STB;
            const size_t kb = (size_t)nt * 64;
            cp_async16(d + st0,       gA0 + kb);
            cp_async16(d + st1,       gA1 + kb);
            cp_async16(d + OPB + st0, gB0 + kb);
            cp_async16(d + OPB + st1, gB1 + kb);
        }
        cp_commit();
        cp_wait<NST - 2>();
        __syncthreads();

        const uint32_t sb = sbase + (tt % NST) * STB;
#pragma unroll
        for (int ks = 0; ks < 2; ks++) {
            uint32_t a[2][4], b[8][2];
            ldsm4(a[0], sb + adA[ks][0]);
            ldsm4(a[1], sb + adA[ks][1]);
#pragma unroll
            for (int j = 0; j < 4; j++) {
                uint32_t tmp[4];
                ldsm4(tmp, sb + OPB + adB[ks][j]);
                b[2*j][0]   = tmp[0]; b[2*j][1]   = tmp[1];
                b[2*j+1][0] = tmp[2]; b[2*j+1][1] = tmp[3];
            }
#pragma unroll
            for (int i = 0; i < 2; i++)
#pragma unroll
                for (int j = 0; j < 8; j++) {
                    if (FP8) mma_e4m3(acc[i][j], a[i], b[j]);
                    else     mma_f16 (acc[i][j], a[i], b[j]);
                }
        }
    }

    // epilogue
    const int row0 = m0 + wm + (lane >> 2);
    const int colb = n0 + wn + (lane & 3) * 2;
    if (mode == 0) {
        __half* Cz = Ch + (size_t)z * sCz;
#pragma unroll
        for (int i = 0; i < 2; i++) {
#pragma unroll
            for (int j = 0; j < 8; j++) {
                const int r0 = row0 + i * 16;
                const int col = colb + j * 8;
                const float* c = acc[i][j];
                __half2 v0; v0.x = __float2half_rn(c[0] * alpha); v0.y = __float2half_rn(c[1] * alpha);
                __half2 v1; v1.x = __float2half_rn(c[2] * alpha); v1.y = __float2half_rn(c[3] * alpha);
                *(__half2*)(Cz + (size_t)r0 * ldc + col)       = v0;
                *(__half2*)(Cz + (size_t)(r0 + 8) * ldc + col) = v1;
            }
        }
    } else {
#pragma unroll
        for (int i = 0; i < 2; i++) {
#pragma unroll
            for (int j = 0; j < 8; j++) {
                const int r0 = row0 + i * 16;
                const int col = colb + j * 8;
                const float* c = acc[i][j];
                *(float2*)(Cf + (size_t)r0 * ldc + col) =
                    make_float2(tanhf(c[0] + bias[col]), tanhf(c[1] + bias[col + 1]));
                *(float2*)(Cf + (size_t)(r0 + 8) * ldc + col) =
                    make_float2(tanhf(c[2] + bias[col]), tanhf(c[3] + bias[col + 1]));
            }
        }
    }
}

// ============================================================================
// fp32 -> e4m3 round, 8 elements per thread
// ============================================================================
__global__ void round8_kernel(const float* __restrict__ X,
                              unsigned char* __restrict__ Y, int count)
{
    int i = (blockIdx.x * blockDim.x + threadIdx.x) * 8;
    if (i >= count) return;
    float4 v0 = *(const float4*)(X + i);
    float4 v1 = *(const float4*)(X + i + 4);
    uint32_t lo = (uint32_t)__nv_cvt_float_to_fp8(v0.x, __NV_SATFINITE, __NV_E4M3)
                | ((uint32_t)__nv_cvt_float_to_fp8(v0.y, __NV_SATFINITE, __NV_E4M3) << 8)
                | ((uint32_t)__nv_cvt_float_to_fp8(v0.z, __NV_SATFINITE, __NV_E4M3) << 16)
                | ((uint32_t)__nv_cvt_float_to_fp8(v0.w, __NV_SATFINITE, __NV_E4M3) << 24);
    uint32_t hi = (uint32_t)__nv_cvt_float_to_fp8(v1.x, __NV_SATFINITE, __NV_E4M3)
                | ((uint32_t)__nv_cvt_float_to_fp8(v1.y, __NV_SATFINITE, __NV_E4M3) << 8)
                | ((uint32_t)__nv_cvt_float_to_fp8(v1.z, __NV_SATFINITE, __NV_E4M3) << 16)
                | ((uint32_t)__nv_cvt_float_to_fp8(v1.w, __NV_SATFINITE, __NV_E4M3) << 24);
    *(uint2*)(Y + i) = make_uint2(lo, hi);
}

// ============================================================================
// fp32 -> fp16 round, elementwise (W only)
// ============================================================================
__global__ void round_kernel(const float* __restrict__ X,
                             __half* __restrict__ hi, int count)
{
    int i = (blockIdx.x * blockDim.x + threadIdx.x) * 4;
    if (i >= count) return;
    float4 v = *(const float4*)(X + i);
    __half2 a; a.x = __float2half_rn(v.x); a.y = __float2half_rn(v.y);
    __half2 b; b.x = __float2half_rn(v.z); b.y = __float2half_rn(v.w);
    *(__half2*)(hi + i)     = a;
    *(__half2*)(hi + i + 2) = b;
}

// ============================================================================
// fp32 [R x C] -> transposed fp16 [C x R]
// ============================================================================
__global__ void round_t_kernel(const float* __restrict__ X, int R, int C,
                               __half* __restrict__ hT)
{
    __shared__ float tile[32][33];
    const int c0 = blockIdx.x * 32;
    const int r0 = blockIdx.y * 32;
    const int tx = threadIdx.x;
    const int ty = threadIdx.y;
#pragma unroll
    for (int j = ty; j < 32; j += 8)
        tile[j][tx] = X[(size_t)(r0 + j) * C + c0 + tx];
    __syncthreads();
#pragma unroll
    for (int j = ty; j < 32; j += 8)
        hT[(size_t)(c0 + j) * R + r0 + tx] = __float2half_rn(tile[tx][j]);
}

// ============================================================================
// merged double softmax with mask; fp16 in/out (in place), grid (NDIM, 3)
// ============================================================================
__device__ __forceinline__ float warp_red_max(float v) {
#pragma unroll
    for (int o = 16; o; o >>= 1) v = fmaxf(v, __shfl_xor_sync(0xffffffffu, v, o));
    return v;
}
__device__ __forceinline__ float warp_red_sum(float v) {
#pragma unroll
    for (int o = 16; o; o >>= 1) v += __shfl_xor_sync(0xffffffffu, v, o);
    return v;
}
template <bool IS_MAX>
__device__ __forceinline__ float block_red(float v, float* red, int t) {
    v = IS_MAX ? warp_red_max(v) : warp_red_sum(v);
    __syncthreads();
    if ((t & 31) == 0) red[t >> 5] = v;
    __syncthreads();
    if (t < 32) {
        float x = (t < 8) ? red[t] : (IS_MAX ? -INFINITY : 0.f);
        x = IS_MAX ? warp_red_max(x) : warp_red_sum(x);
        if (t == 0) red[0] = x;
    }
    __syncthreads();
    return red[0];
}

__global__ void __launch_bounds__(256) softmax2_kernel(
    __half* __restrict__ Sbase,
    const float* __restrict__ Lm,
    const unsigned char* __restrict__ MT,
    const float* __restrict__ Bhigh)
{
    __shared__ __align__(16) float buf[NDIM];
    __shared__ float red[32];
    const int t = threadIdx.x;
    const int row = blockIdx.x;
    const int br = blockIdx.y;
    __half* Srow = Sbase + (size_t)br * NDIM * NDIM + (size_t)row * NDIM;
    const float* maskf = (br == 0) ? (Lm + (size_t)row * NDIM)
                       : (br == 2) ? (Bhigh + (size_t)row * NDIM) : nullptr;
    const unsigned char* maskb = (br == 1) ? (MT + (size_t)row * NDIM) : nullptr;

    float mx = -INFINITY;
#pragma unroll
    for (int i = t * 8; i < NDIM; i += 2048) {
        uint4 raw = *(const uint4*)(Srow + i);
        const __half2* h2 = (const __half2*)&raw;
#pragma unroll
        for (int q = 0; q < 4; q++) {
            float2 f = __half22float2(h2[q]);
            buf[i + 2*q]     = f.x;
            buf[i + 2*q + 1] = f.y;
            mx = fmaxf(mx, fmaxf(f.x, f.y));
        }
    }
    const float smax = block_red<true>(mx, red, t);

    float sum = 0.f;
#pragma unroll
    for (int i = t * 4; i < NDIM; i += 1024) {
        float4 v = *(float4*)&buf[i];
        v.x = __expf(v.x - smax); v.y = __expf(v.y - smax);
        v.z = __expf(v.z - smax); v.w = __expf(v.w - smax);
        *(float4*)&buf[i] = v;
        sum += v.x + v.y + v.z + v.w;
    }
    const float inv = 1.f / block_red<false>(sum, red, t);

    float mx2 = -INFINITY;
#pragma unroll
    for (int i = t * 4; i < NDIM; i += 1024) {
        float4 v = *(float4*)&buf[i];
        float4 m;
        if (maskf) {
            float4 mm = *(const float4*)(maskf + i);
            m.x = (mm.x != 0.f) ? 1.f : 0.f;
            m.y = (mm.y != 0.f) ? 1.f : 0.f;
            m.z = (mm.z != 0.f) ? 1.f : 0.f;
            m.w = (mm.w != 0.f) ? 1.f : 0.f;
        } else {
            uchar4 mm = *(const uchar4*)(maskb + i);
            m.x = (float)mm.x; m.y = (float)mm.y; m.z = (float)mm.z; m.w = (float)mm.w;
        }
        v.x = v.x * inv * m.x; v.y = v.y * inv * m.y;
        v.z = v.z * inv * m.z; v.w = v.w * inv * m.w;
        *(float4*)&buf[i] = v;
        mx2 = fmaxf(mx2, fmaxf(fmaxf(v.x, v.y), fmaxf(v.z, v.w)));
    }
    const float smax2 = block_red<true>(mx2, red, t);

    float sum2 = 0.f;
#pragma unroll
    for (int i = t * 4; i < NDIM; i += 1024) {
        float4 v = *(float4*)&buf[i];
        v.x = __expf(v.x - smax2); v.y = __expf(v.y - smax2);
        v.z = __expf(v.z - smax2); v.w = __expf(v.w - smax2);
        *(float4*)&buf[i] = v;
        sum2 += v.x + v.y + v.z + v.w;
    }
    const float inv2 = 1.f / block_red<false>(sum2, red, t);

#pragma unroll
    for (int i = t * 8; i < NDIM; i += 2048) {
        uint4 raw;
        __half2* h2 = (__half2*)&raw;
#pragma unroll
        for (int q = 0; q < 4; q++) {
            h2[q].x = __float2half_rn(buf[i + 2*q] * inv2);
            h2[q].y = __float2half_rn(buf[i + 2*q + 1] * inv2);
        }
        *(uint4*)(Srow + i) = raw;
    }
}

// ============================================================================
// transposed byte mask: MT[r][c] = (B[c][r] != 0)
// ============================================================================
__global__ void mask_transpose_kernel(const float* __restrict__ B,
                                      unsigned char* __restrict__ MT)
{
    __shared__ unsigned char tile[32][33];
    const int bx = blockIdx.x * 32;
    const int by = blockIdx.y * 32;
    const int tx = threadIdx.x;
    const int ty = threadIdx.y;
#pragma unroll
    for (int j = ty; j < 32; j += 8)
        tile[j][tx] = (B[(size_t)(by + j) * NDIM + bx + tx] != 0.f) ? 1 : 0;
    __syncthreads();
#pragma unroll
    for (int j = ty; j < 32; j += 8)
        MT[(size_t)(bx + j) * NDIM + by + tx] = tile[tx][j];
}

// ============================================================================
// launch
// ============================================================================
extern "C" void kernel_launch(void* const* d_in, const int* in_sizes, int n_in,
                              void* d_out, int out_size)
{
    const float* L      = (const float*)d_in[0];
    const float* H      = (const float*)d_in[1];
    const float* B_low  = (const float*)d_in[2];
    const float* H_low  = (const float*)d_in[3];
    const float* B_high = (const float*)d_in[4];
    const float* H_high = (const float*)d_in[5];
    const float* W      = (const float*)d_in[6];
    const float* bvec   = (const float*)d_in[7];
    float* out = (float*)d_out;

    __half *Sh, *HT, *H4, *Wh;
    unsigned char *H8, *MT;
    cudaGetSymbolAddress((void**)&Sh, g_Sh);
    cudaGetSymbolAddress((void**)&H8, g_H8);
    cudaGetSymbolAddress((void**)&HT, g_HT);
    cudaGetSymbolAddress((void**)&H4, g_H4);
    cudaGetSymbolAddress((void**)&Wh, g_Wh);
    cudaGetSymbolAddress((void**)&MT, g_MT);

    const size_t HSZ = (size_t)NDIM * DDIM;
    const size_t NN  = (size_t)NDIM * NDIM;
    const float scale = 0.03125f;  // 1/sqrt(1024)
    const int rt = 256;

    // [0..2] e4m3 rounds of H, H_low, H_high
    round8_kernel<<<(int)(HSZ / 8 / rt), rt>>>(H,      H8 + 0 * HSZ, (int)HSZ);
    round8_kernel<<<(int)(HSZ / 8 / rt), rt>>>(H_low,  H8 + 1 * HSZ, (int)HSZ);
    round8_kernel<<<(int)(HSZ / 8 / rt), rt>>>(H_high, H8 + 2 * HSZ, (int)HSZ);
    // [3] W fp16 round, [4] transposed mask
    round_kernel<<<(int)((size_t)DDIM * 3 * DDIM / 4 / rt), rt>>>(
        W, Wh, (int)((size_t)DDIM * 3 * DDIM));
    mask_transpose_kernel<<<dim3(NDIM / 32, NDIM / 32), dim3(32, 8)>>>(B_low, MT);

    // [5] merged fp8 score GEMM: S_z = scale * H8[0] @ H8[z]^T
    gemm_tcore<true><<<dim3(NDIM / 128, NDIM / 128, 3), 256>>>(
        H8, 0, DDIM, H8, HSZ, DDIM,
        DDIM, 0, scale, Sh, nullptr, NN, NDIM, nullptr);

    // [6..8] transposed fp16 KV copies
    round_t_kernel<<<dim3(DDIM / 32, NDIM / 32), dim3(32, 8)>>>(H,      NDIM, DDIM, HT + 0 * HSZ);
    round_t_kernel<<<dim3(DDIM / 32, NDIM / 32), dim3(32, 8)>>>(H_low,  NDIM, DDIM, HT + 1 * HSZ);
    round_t_kernel<<<dim3(DDIM / 32, NDIM / 32), dim3(32, 8)>>>(H_high, NDIM, DDIM, HT + 2 * HSZ);

    // [9] merged double softmax (in place, fp16)
    softmax2_kernel<<<dim3(NDIM, 3), 256>>>(Sh, L, MT, B_high);

    // [10] merged fp16 AV GEMM: H4[:, zD:(z+1)D] = P_z @ KV_z
    gemm_tcore<false><<<dim3(DDIM / 128, NDIM / 128, 3), 256>>>(
        Sh, NN, NDIM, HT, HSZ, NDIM,
        NDIM, 0, 1.0f, H4, nullptr, DDIM, 3 * DDIM, nullptr);

    // [11] fp16 output GEMM: out = tanh(H4 @ W^T + b)
    gemm_tcore<false><<<dim3(DDIM / 128, NDIM / 128, 1), 256>>>(
        H4, 0, 3 * DDIM, Wh, 0, 3 * DDIM,
        3 * DDIM, 1, 1.0f, nullptr, out, 0, DDIM, bvec);
}

// round 8
// speedup vs baseline: 6.3326x; 1.0043x over previous
#include <cuda_runtime.h>
#include <cuda_fp16.h>
#include <math.h>
#include <stdint.h>

#define NDIM 4096
#define DDIM 1024

// ---------------- scratch (device globals) ----------------
__device__ __half g_Sh[3][(size_t)NDIM * NDIM];            // fp16 scores -> probs (in place)
__device__ __half g_Hh[3][(size_t)NDIM * DDIM];            // fp16(H / H_low / H_high) row-major
__device__ __half g_HT[3][(size_t)DDIM * NDIM];            // fp16 transposed KV
__device__ __half g_H4[(size_t)NDIM * 3 * DDIM];           // fp16 concat AV outputs
__device__ __half g_Wh[(size_t)DDIM * 3 * DDIM];           // fp16(W)
__device__ unsigned char g_MT[(size_t)NDIM * NDIM];        // (B_low!=0)^T byte mask

// ---------------- PTX helpers (portable tier) ----------------
__device__ __forceinline__ uint32_t smem_u32(const void* p) {
    uint32_t a;
    asm("{ .reg .u64 t; cvta.to.shared.u64 t, %1; cvt.u32.u64 %0, t; }" : "=r"(a) : "l"(p));
    return a;
}
__device__ __forceinline__ void cp_async16(uint32_t dst, const void* src) {
    asm volatile("cp.async.cg.shared.global [%0], [%1], 16;" :: "r"(dst), "l"(src) : "memory");
}
__device__ __forceinline__ void cp_commit() {
    asm volatile("cp.async.commit_group;" ::: "memory");
}
template <int N>
__device__ __forceinline__ void cp_wait() {
    asm volatile("cp.async.wait_group %0;" :: "n"(N) : "memory");
}
__device__ __forceinline__ void ldsm4(uint32_t* d, uint32_t addr) {
    asm volatile("ldmatrix.sync.aligned.m8n8.x4.shared.b16 {%0,%1,%2,%3}, [%4];"
        : "=r"(d[0]), "=r"(d[1]), "=r"(d[2]), "=r"(d[3]) : "r"(addr));
}
// f32-accum HMMA
__device__ __forceinline__ void mma_f32(float* c, const uint32_t* a, const uint32_t* b) {
    asm volatile("mma.sync.aligned.m16n8k16.row.col.f32.f16.f16.f32 "
        "{%0,%1,%2,%3}, {%4,%5,%6,%7}, {%8,%9}, {%0,%1,%2,%3};"
        : "+f"(c[0]), "+f"(c[1]), "+f"(c[2]), "+f"(c[3])
        : "r"(a[0]), "r"(a[1]), "r"(a[2]), "r"(a[3]), "r"(b[0]), "r"(b[1]));
}
// f16-accum HMMA (rate experiment)
__device__ __forceinline__ void mma_f16acc(uint32_t* c, const uint32_t* a, const uint32_t* b) {
    asm volatile("mma.sync.aligned.m16n8k16.row.col.f16.f16.f16.f16 "
        "{%0,%1}, {%2,%3,%4,%5}, {%6,%7}, {%0,%1};"
        : "+r"(c[0]), "+r"(c[1])
        : "r"(a[0]), "r"(a[1]), "r"(a[2]), "r"(a[3]), "r"(b[0]), "r"(b[1]));
}

// SMEM tile: 128 rows x 32 fp16 (64B/row), four 16B chunks/row, XOR swizzle.
__device__ __forceinline__ uint32_t soff64(int r, int c) {
    return (uint32_t)(r * 64 + ((c ^ ((r >> 1) & 3)) << 4));
}

#define OPB (128 * 64)      // 8192 B per operand tile per stage
#define STB (2 * OPB)       // 16 KB per stage (A, B)
#define NST 3               // 48 KB static smem, exact
#define BKE 32              // fp16 k-elements per stage

// ============================================================================
// HMMA NT GEMM, fp16 inputs.  ACC16: f16 accumulators (scores; scale in epi).
//                            !ACC16: f32 accumulators.
// mode 0: Ch = fp16(alpha * acc)      mode 1 (!ACC16 only): Cf = tanh(acc + bias[n])
// ============================================================================
template <bool ACC16>
__global__ void __launch_bounds__(256, 2) gemm_tcore(
    const __half* __restrict__ A, size_t sAz, int lda,
    const __half* __restrict__ B, size_t sBz, int ldb,
    int K, int mode, float alpha,
    __half* __restrict__ Ch, float* __restrict__ Cf, size_t sCz, int ldc,
    const float* __restrict__ bias)
{
    __shared__ __align__(128) char sm[NST * STB];

    const int t    = threadIdx.x;
    const int lane = t & 31;
    const int wid  = t >> 5;
    const int wm   = (wid & 3) * 32;
    const int wn   = (wid >> 2) * 64;
    const int m0   = blockIdx.y * 128;
    const int n0   = blockIdx.x * 128;
    const int z    = blockIdx.z;
    A += (size_t)z * sAz;
    B += (size_t)z * sBz;
    const uint32_t sbase = smem_u32(sm);

    // loader: thread t covers 16B chunk (rl, cl) and (rl+64, cl) of each operand
    const int rl = t >> 2;
    const int cl = t & 3;
    const uint32_t st0 = soff64(rl, cl);
    const uint32_t st1 = soff64(rl + 64, cl);
    const __half* gA0 = A + (size_t)(m0 + rl) * lda + cl * 8;
    const __half* gA1 = A + (size_t)(m0 + rl + 64) * lda + cl * 8;
    const __half* gB0 = B + (size_t)(n0 + rl) * ldb + cl * 8;
    const __half* gB1 = B + (size_t)(n0 + rl + 64) * ldb + cl * 8;

    // fragment smem offsets, both k-steps of a stage
    uint32_t adA[2][2], adB[2][4];
    {
        const int mm = lane >> 3;
#pragma unroll
        for (int ks = 0; ks < 2; ks++) {
#pragma unroll
            for (int i = 0; i < 2; i++)
                adA[ks][i] = soff64(wm + i * 16 + (mm & 1) * 8 + (lane & 7),
                                    2 * ks + (mm >> 1));
#pragma unroll
            for (int j = 0; j < 4; j++)
                adB[ks][j] = soff64(wn + j * 16 + (mm >> 1) * 8 + (lane & 7),
                                    2 * ks + (mm & 1));
        }
    }

    float    accf[2][8][4];
    uint32_t acch[2][8][2];
#pragma unroll
    for (int i = 0; i < 2; i++)
#pragma unroll
        for (int j = 0; j < 8; j++) {
            if (ACC16) { acch[i][j][0] = 0u; acch[i][j][1] = 0u; }
            else {
#pragma unroll
                for (int q = 0; q < 4; q++) accf[i][j][q] = 0.f;
            }
        }

    const int T = K / BKE;

    // prologue
#pragma unroll
    for (int s = 0; s < NST - 1; s++) {
        const uint32_t d = sbase + s * STB;
        const int k = s * BKE;
        cp_async16(d + st0,       gA0 + k);
        cp_async16(d + st1,       gA1 + k);
        cp_async16(d + OPB + st0, gB0 + k);
        cp_async16(d + OPB + st1, gB1 + k);
        cp_commit();
    }

    for (int tt = 0; tt < T; tt++) {
        __syncthreads();
        const int nt = tt + NST - 1;
        if (nt < T) {
            const uint32_t d = sbase + (nt % NST) * STB;
            const int k = nt * BKE;
            cp_async16(d + st0,       gA0 + k);
            cp_async16(d + st1,       gA1 + k);
            cp_async16(d + OPB + st0, gB0 + k);
            cp_async16(d + OPB + st1, gB1 + k);
        }
        cp_commit();
        cp_wait<NST - 2>();
        __syncthreads();

        const uint32_t sb = sbase + (tt % NST) * STB;
#pragma unroll
        for (int ks = 0; ks < 2; ks++) {
            uint32_t a[2][4], b[8][2];
            ldsm4(a[0], sb + adA[ks][0]);
            ldsm4(a[1], sb + adA[ks][1]);
#pragma unroll
            for (int j = 0; j < 4; j++) {
                uint32_t tmp[4];
                ldsm4(tmp, sb + OPB + adB[ks][j]);
                b[2*j][0]   = tmp[0]; b[2*j][1]   = tmp[1];
                b[2*j+1][0] = tmp[2]; b[2*j+1][1] = tmp[3];
            }
#pragma unroll
            for (int i = 0; i < 2; i++)
#pragma unroll
                for (int j = 0; j < 8; j++) {
                    if (ACC16) mma_f16acc(acch[i][j], a[i], b[j]);
                    else       mma_f32  (accf[i][j], a[i], b[j]);
                }
        }
    }

    // epilogue
    const int row0 = m0 + wm + (lane >> 2);
    const int colb = n0 + wn + (lane & 3) * 2;
    if (ACC16) {
        __half* Cz = Ch + (size_t)z * sCz;
        const __half2 sc2 = __float2half2_rn(alpha);
#pragma unroll
        for (int i = 0; i < 2; i++) {
#pragma unroll
            for (int j = 0; j < 8; j++) {
                const int r0 = row0 + i * 16;
                const int col = colb + j * 8;
                __half2 v0 = __hmul2(*(__half2*)&acch[i][j][0], sc2);
                __half2 v1 = __hmul2(*(__half2*)&acch[i][j][1], sc2);
                *(__half2*)(Cz + (size_t)r0 * ldc + col)       = v0;
                *(__half2*)(Cz + (size_t)(r0 + 8) * ldc + col) = v1;
            }
        }
    } else if (mode == 0) {
        __half* Cz = Ch + (size_t)z * sCz;
#pragma unroll
        for (int i = 0; i < 2; i++) {
#pragma unroll
            for (int j = 0; j < 8; j++) {
                const int r0 = row0 + i * 16;
                const int col = colb + j * 8;
                const float* c = accf[i][j];
                __half2 v0; v0.x = __float2half_rn(c[0] * alpha); v0.y = __float2half_rn(c[1] * alpha);
                __half2 v1; v1.x = __float2half_rn(c[2] * alpha); v1.y = __float2half_rn(c[3] * alpha);
                *(__half2*)(Cz + (size_t)r0 * ldc + col)       = v0;
                *(__half2*)(Cz + (size_t)(r0 + 8) * ldc + col) = v1;
            }
        }
    } else {
#pragma unroll
        for (int i = 0; i < 2; i++) {
#pragma unroll
            for (int j = 0; j < 8; j++) {
                const int r0 = row0 + i * 16;
                const int col = colb + j * 8;
                const float* c = accf[i][j];
                *(float2*)(Cf + (size_t)r0 * ldc + col) =
                    make_float2(tanhf(c[0] + bias[col]), tanhf(c[1] + bias[col + 1]));
                *(float2*)(Cf + (size_t)(r0 + 8) * ldc + col) =
                    make_float2(tanhf(c[2] + bias[col]), tanhf(c[3] + bias[col + 1]));
            }
        }
    }
}

// ============================================================================
// merged fp32 -> fp16 round of the 3 H tensors, grid (blocks, 3)
// ============================================================================
__global__ void roundH_kernel(const float* __restrict__ X0,
                              const float* __restrict__ X1,
                              const float* __restrict__ X2,
                              __half* __restrict__ Y, int per)
{
    const int zz = blockIdx.y;
    const float* X = (zz == 0) ? X0 : (zz == 1) ? X1 : X2;
    __half* Yz = Y + (size_t)zz * per;
    int i = (blockIdx.x * blockDim.x + threadIdx.x) * 4;
    if (i >= per) return;
    float4 v = *(const float4*)(X + i);
    __half2 a; a.x = __float2half_rn(v.x); a.y = __float2half_rn(v.y);
    __half2 b; b.x = __float2half_rn(v.z); b.y = __float2half_rn(v.w);
    *(__half2*)(Yz + i)     = a;
    *(__half2*)(Yz + i + 2) = b;
}

// fp32 -> fp16 round (W)
__global__ void round_kernel(const float* __restrict__ X,
                             __half* __restrict__ hi, int count)
{
    int i = (blockIdx.x * blockDim.x + threadIdx.x) * 4;
    if (i >= count) return;
    float4 v = *(const float4*)(X + i);
    __half2 a; a.x = __float2half_rn(v.x); a.y = __float2half_rn(v.y);
    __half2 b; b.x = __float2half_rn(v.z); b.y = __float2half_rn(v.w);
    *(__half2*)(hi + i)     = a;
    *(__half2*)(hi + i + 2) = b;
}

// ============================================================================
// merged fp32 [R x C] -> transposed fp16 [C x R], grid (..., ..., 3)
// ============================================================================
__global__ void round_t3_kernel(const float* __restrict__ X0,
                                const float* __restrict__ X1,
                                const float* __restrict__ X2,
                                __half* __restrict__ hT, int R, int C)
{
    __shared__ float tile[32][33];
    const int zz = blockIdx.z;
    const float* X = (zz == 0) ? X0 : (zz == 1) ? X1 : X2;
    __half* out = hT + (size_t)zz * R * C;
    const int c0 = blockIdx.x * 32;
    const int r0 = blockIdx.y * 32;
    const int tx = threadIdx.x;
    const int ty = threadIdx.y;
#pragma unroll
    for (int j = ty; j < 32; j += 8)
        tile[j][tx] = X[(size_t)(r0 + j) * C + c0 + tx];
    __syncthreads();
#pragma unroll
    for (int j = ty; j < 32; j += 8)
        out[(size_t)(c0 + j) * R + r0 + tx] = __float2half_rn(tile[tx][j]);
}

// ============================================================================
// merged double softmax with mask; fp16 in/out (in place), grid (NDIM, 3)
// ============================================================================
__device__ __forceinline__ float warp_red_max(float v) {
#pragma unroll
    for (int o = 16; o; o >>= 1) v = fmaxf(v, __shfl_xor_sync(0xffffffffu, v, o));
    return v;
}
__device__ __forceinline__ float warp_red_sum(float v) {
#pragma unroll
    for (int o = 16; o; o >>= 1) v += __shfl_xor_sync(0xffffffffu, v, o);
    return v;
}
template <bool IS_MAX>
__device__ __forceinline__ float block_red(float v, float* red, int t) {
    v = IS_MAX ? warp_red_max(v) : warp_red_sum(v);
    __syncthreads();
    if ((t & 31) == 0) red[t >> 5] = v;
    __syncthreads();
    if (t < 32) {
        float x = (t < 8) ? red[t] : (IS_MAX ? -INFINITY : 0.f);
        x = IS_MAX ? warp_red_max(x) : warp_red_sum(x);
        if (t == 0) red[0] = x;
    }
    __syncthreads();
    return red[0];
}

__global__ void __launch_bounds__(256) softmax2_kernel(
    __half* __restrict__ Sbase,
    const float* __restrict__ Lm,
    const unsigned char* __restrict__ MT,
    const float* __restrict__ Bhigh)
{
    __shared__ __align__(16) float buf[NDIM];
    __shared__ float red[32];
    const int t = threadIdx.x;
    const int row = blockIdx.x;
    const int br = blockIdx.y;
    __half* Srow = Sbase + (size_t)br * NDIM * NDIM + (size_t)row * NDIM;
    const float* maskf = (br == 0) ? (Lm + (size_t)row * NDIM)
                       : (br == 2) ? (Bhigh + (size_t)row * NDIM) : nullptr;
    const unsigned char* maskb = (br == 1) ? (MT + (size_t)row * NDIM) : nullptr;

    float mx = -INFINITY;
#pragma unroll
    for (int i = t * 8; i < NDIM; i += 2048) {
        uint4 raw = *(const uint4*)(Srow + i);
        const __half2* h2 = (const __half2*)&raw;
#pragma unroll
        for (int q = 0; q < 4; q++) {
            float2 f = __half22float2(h2[q]);
            buf[i + 2*q]     = f.x;
            buf[i + 2*q + 1] = f.y;
            mx = fmaxf(mx, fmaxf(f.x, f.y));
        }
    }
    const float smax = block_red<true>(mx, red, t);

    float sum = 0.f;
#pragma unroll
    for (int i = t * 4; i < NDIM; i += 1024) {
        float4 v = *(float4*)&buf[i];
        v.x = __expf(v.x - smax); v.y = __expf(v.y - smax);
        v.z = __expf(v.z - smax); v.w = __expf(v.w - smax);
        *(float4*)&buf[i] = v;
        sum += v.x + v.y + v.z + v.w;
    }
    const float inv = 1.f / block_red<false>(sum, red, t);

    float mx2 = -INFINITY;
#pragma unroll
    for (int i = t * 4; i < NDIM; i += 1024) {
        float4 v = *(float4*)&buf[i];
        float4 m;
        if (maskf) {
            float4 mm = *(const float4*)(maskf + i);
            m.x = (mm.x != 0.f) ? 1.f : 0.f;
            m.y = (mm.y != 0.f) ? 1.f : 0.f;
            m.z = (mm.z != 0.f) ? 1.f : 0.f;
            m.w = (mm.w != 0.f) ? 1.f : 0.f;
        } else {
            uchar4 mm = *(const uchar4*)(maskb + i);
            m.x = (float)mm.x; m.y = (float)mm.y; m.z = (float)mm.z; m.w = (float)mm.w;
        }
        v.x = v.x * inv * m.x; v.y = v.y * inv * m.y;
        v.z = v.z * inv * m.z; v.w = v.w * inv * m.w;
        *(float4*)&buf[i] = v;
        mx2 = fmaxf(mx2, fmaxf(fmaxf(v.x, v.y), fmaxf(v.z, v.w)));
    }
    const float smax2 = block_red<true>(mx2, red, t);

    float sum2 = 0.f;
#pragma unroll
    for (int i = t * 4; i < NDIM; i += 1024) {
        float4 v = *(float4*)&buf[i];
        v.x = __expf(v.x - smax2); v.y = __expf(v.y - smax2);
        v.z = __expf(v.z - smax2); v.w = __expf(v.w - smax2);
        *(float4*)&buf[i] = v;
        sum2 += v.x + v.y + v.z + v.w;
    }
    const float inv2 = 1.f / block_red<false>(sum2, red, t);

#pragma unroll
    for (int i = t * 8; i < NDIM; i += 2048) {
        uint4 raw;
        __half2* h2 = (__half2*)&raw;
#pragma unroll
        for (int q = 0; q < 4; q++) {
            h2[q].x = __float2half_rn(buf[i + 2*q] * inv2);
            h2[q].y = __float2half_rn(buf[i + 2*q + 1] * inv2);
        }
        *(uint4*)(Srow + i) = raw;
    }
}

// ============================================================================
// transposed byte mask: MT[r][c] = (B[c][r] != 0)
// ============================================================================
__global__ void mask_transpose_kernel(const float* __restrict__ B,
                                      unsigned char* __restrict__ MT)
{
    __shared__ unsigned char tile[32][33];
    const int bx = blockIdx.x * 32;
    const int by = blockIdx.y * 32;
    const int tx = threadIdx.x;
    const int ty = threadIdx.y;
#pragma unroll
    for (int j = ty; j < 32; j += 8)
        tile[j][tx] = (B[(size_t)(by + j) * NDIM + bx + tx] != 0.f) ? 1 : 0;
    __syncthreads();
#pragma unroll
    for (int j = ty; j < 32; j += 8)
        MT[(size_t)(bx + j) * NDIM + by + tx] = tile[tx][j];
}

// ============================================================================
// launch
// ============================================================================
extern "C" void kernel_launch(void* const* d_in, const int* in_sizes, int n_in,
                              void* d_out, int out_size)
{
    const float* L      = (const float*)d_in[0];
    const float* H      = (const float*)d_in[1];
    const float* B_low  = (const float*)d_in[2];
    const float* H_low  = (const float*)d_in[3];
    const float* B_high = (const float*)d_in[4];
    const float* H_high = (const float*)d_in[5];
    const float* W      = (const float*)d_in[6];
    const float* bvec   = (const float*)d_in[7];
    float* out = (float*)d_out;

    __half *Sh, *Hh, *HT, *H4, *Wh;
    unsigned char* MT;
    cudaGetSymbolAddress((void**)&Sh, g_Sh);
    cudaGetSymbolAddress((void**)&Hh, g_Hh);
    cudaGetSymbolAddress((void**)&HT, g_HT);
    cudaGetSymbolAddress((void**)&H4, g_H4);
    cudaGetSymbolAddress((void**)&Wh, g_Wh);
    cudaGetSymbolAddress((void**)&MT, g_MT);

    const size_t HSZ = (size_t)NDIM * DDIM;
    const size_t NN  = (size_t)NDIM * NDIM;
    const float scale = 0.03125f;  // 1/sqrt(1024)
    const int rt = 256;

    // [0] merged fp16 rounds of H, H_low, H_high
    roundH_kernel<<<dim3((unsigned)(HSZ / 4 / rt), 3), rt>>>(H, H_low, H_high, Hh, (int)HSZ);
    // [1] transposed mask (needed by softmax branch 1)
    mask_transpose_kernel<<<dim3(NDIM / 32, NDIM / 32), dim3(32, 8)>>>(B_low, MT);

    // [2] merged score GEMM, f16 accumulators: S_z = scale * H @ Hh_z^T
    gemm_tcore<true><<<dim3(NDIM / 128, NDIM / 128, 3), 256>>>(
        Hh, 0, DDIM, Hh, HSZ, DDIM,
        DDIM, 0, scale, Sh, nullptr, NN, NDIM, nullptr);

    // [3] merged double softmax (in place, fp16)
    softmax2_kernel<<<dim3(NDIM, 3), 256>>>(Sh, L, MT, B_high);

    // [4] merged transposed fp16 KV copies
    round_t3_kernel<<<dim3(DDIM / 32, NDIM / 32, 3), dim3(32, 8)>>>(
        H, H_low, H_high, HT, NDIM, DDIM);

    // [5] merged AV GEMM (ncu -s 5 target), f32 accumulators
    gemm_tcore<false><<<dim3(DDIM / 128, NDIM / 128, 3), 256>>>(
        Sh, NN, NDIM, HT, HSZ, NDIM,
        NDIM, 0, 1.0f, H4, nullptr, DDIM, 3 * DDIM, nullptr);

    // [6] W fp16 round
    round_kernel<<<(int)((size_t)DDIM * 3 * DDIM / 4 / rt), rt>>>(
        W, Wh, (int)((size_t)DDIM * 3 * DDIM));

    // [7] output GEMM: out = tanh(H4 @ W^T + b), f32 accumulators
    gemm_tcore<false><<<dim3(DDIM / 128, NDIM / 128, 1), 256>>>(
        H4, 0, 3 * DDIM, Wh, 0, 3 * DDIM,
        3 * DDIM, 1, 1.0f, nullptr, out, 0, DDIM, bvec);
}